// round 1
// baseline (speedup 1.0000x reference)
#include <cuda_runtime.h>
#include <cuda_bf16.h>
#include <math.h>

// Problem constants
#define B_   16
#define C_   256
#define S_   1024      // 32*32 tokens
#define H_   4         // heads
#define D_   64        // d_k
#define O3_  768       // 3*H_*D_
#define SCALE_ 0.125f  // 64^-0.5

// Scratch (static device allocations are allowed)
__device__ float g_qkv[B_ * S_ * O3_];   // [b][s][768], head-major: o = h*192 + {q:0..63, k:64..127, v:128..191}
__device__ float g_ao [B_ * S_ * C_];    // attention output [b][s][256] (h*64+d)

// ---------------------------------------------------------------------------
// Kernel 1: QKV projection.  qkv[b,s,o] = sum_c x[b,c,s] * w_proj[c,o] + b_proj[o]
// A(m,k) = x[b, k*S + m]  (contiguous along m), B(k,n) = w_proj[k*768+n]
// 128x128x8 tiles, 256 threads, 8x8 register microtiles.
// ---------------------------------------------------------------------------
__global__ void __launch_bounds__(256) qkv_gemm_kernel(const float* __restrict__ x,
                                                       const float* __restrict__ wp,
                                                       const float* __restrict__ bp) {
    __shared__ float As[8][132];
    __shared__ float Bs[8][132];

    const int b  = blockIdx.z;
    const int m0 = blockIdx.y * 128;
    const int n0 = blockIdx.x * 128;
    const float* xb = x + (size_t)b * C_ * S_;

    const int tid = threadIdx.x;
    const int tx = tid & 15;        // 0..15, column group
    const int ty = tid >> 4;        // 0..15, row group

    float acc[8][8];
#pragma unroll
    for (int r = 0; r < 8; r++)
#pragma unroll
        for (int c = 0; c < 8; c++) acc[r][c] = 0.f;

    const int a_mm = tid & 127, a_k2 = tid >> 7;   // A loader: m contiguous
    const int b_nn = tid & 127, b_k2 = tid >> 7;   // B loader: n contiguous

    for (int k0 = 0; k0 < C_; k0 += 8) {
#pragma unroll
        for (int p = 0; p < 4; p++) {
            int kk = a_k2 + p * 2;
            As[kk][a_mm] = xb[(size_t)(k0 + kk) * S_ + m0 + a_mm];
        }
#pragma unroll
        for (int p = 0; p < 4; p++) {
            int kk = b_k2 + p * 2;
            Bs[kk][b_nn] = wp[(size_t)(k0 + kk) * O3_ + n0 + b_nn];
        }
        __syncthreads();

#pragma unroll
        for (int kk = 0; kk < 8; kk++) {
            float a[8], bb[8];
            *(float4*)(a)     = *(const float4*)&As[kk][ty * 8];
            *(float4*)(a + 4) = *(const float4*)&As[kk][ty * 8 + 4];
            *(float4*)(bb)     = *(const float4*)&Bs[kk][tx * 8];
            *(float4*)(bb + 4) = *(const float4*)&Bs[kk][tx * 8 + 4];
#pragma unroll
            for (int r = 0; r < 8; r++)
#pragma unroll
                for (int c = 0; c < 8; c++) acc[r][c] = fmaf(a[r], bb[c], acc[r][c]);
        }
        __syncthreads();
    }

    // Epilogue: add bias, store row-major [s][768]
    float bias[8];
    *(float4*)(bias)     = *(const float4*)&bp[n0 + tx * 8];
    *(float4*)(bias + 4) = *(const float4*)&bp[n0 + tx * 8 + 4];
    float* qb = g_qkv + (size_t)b * S_ * O3_;
#pragma unroll
    for (int r = 0; r < 8; r++) {
        float* row = qb + (size_t)(m0 + ty * 8 + r) * O3_ + n0 + tx * 8;
        float4 v0, v1;
        v0.x = acc[r][0] + bias[0]; v0.y = acc[r][1] + bias[1];
        v0.z = acc[r][2] + bias[2]; v0.w = acc[r][3] + bias[3];
        v1.x = acc[r][4] + bias[4]; v1.y = acc[r][5] + bias[5];
        v1.z = acc[r][6] + bias[6]; v1.w = acc[r][7] + bias[7];
        *(float4*)(row)     = v0;
        *(float4*)(row + 4) = v1;
    }
}

// ---------------------------------------------------------------------------
// Kernel 2: flash-style attention, one CTA per (q-tile of 64 rows, head, batch).
// 256 threads; thread (ty,tx) owns a 4x4 tile of the 64x64 score block and a
// 4x4 tile of the 64x64 output block. Online softmax over 16 j-tiles.
// ---------------------------------------------------------------------------
#define PADW 68
__global__ void __launch_bounds__(256) attn_kernel() {
    extern __shared__ float sm[];
    float* Qs = sm;                 // [d][i], stride PADW
    float* Ks = sm + 64 * PADW;     // [d][j]
    float* Vs = sm + 2 * 64 * PADW; // [j][d]
    float* Ps = sm + 3 * 64 * PADW; // [i][j]

    const int i0 = blockIdx.x * 64;
    const int h  = blockIdx.y;
    const int b  = blockIdx.z;
    const float* qkv = g_qkv + (size_t)b * S_ * O3_;

    const int tid = threadIdx.x;
    const int tx = tid & 15, ty = tid >> 4;
    const int ld = tid & 63;   // d (or d/j inner) lane for loads
    const int lr = tid >> 6;   // 0..3

    // Load Q tile (64 rows x 64 d) transposed into Qs[d][i]
#pragma unroll
    for (int p = 0; p < 16; p++) {
        int i = lr + p * 4;
        Qs[ld * PADW + i] = qkv[(size_t)(i0 + i) * O3_ + h * 192 + ld];
    }

    float O[4][4];
    float m_old[4], lsum[4];
#pragma unroll
    for (int r = 0; r < 4; r++) {
        m_old[r] = -1e30f; lsum[r] = 0.f;
#pragma unroll
        for (int c = 0; c < 4; c++) O[r][c] = 0.f;
    }

    for (int jt = 0; jt < 16; jt++) {
        __syncthreads();   // previous PV gemm done before overwriting K/V
        const int j0 = jt * 64;
#pragma unroll
        for (int p = 0; p < 16; p++) {
            int j = lr + p * 4;
            const float* base = &qkv[(size_t)(j0 + j) * O3_ + h * 192 + ld];
            Ks[ld * PADW + j] = base[64];    // K
            Vs[j * PADW + ld] = base[128];   // V
        }
        __syncthreads();

        // S tile = Q K^T * scale
        float sacc[4][4];
#pragma unroll
        for (int r = 0; r < 4; r++)
#pragma unroll
            for (int c = 0; c < 4; c++) sacc[r][c] = 0.f;

#pragma unroll
        for (int d = 0; d < 64; d++) {
            float4 a  = *(const float4*)&Qs[d * PADW + ty * 4];
            float4 bk = *(const float4*)&Ks[d * PADW + tx * 4];
            float ar[4] = {a.x, a.y, a.z, a.w};
            float bc[4] = {bk.x, bk.y, bk.z, bk.w};
#pragma unroll
            for (int r = 0; r < 4; r++)
#pragma unroll
                for (int c = 0; c < 4; c++) sacc[r][c] = fmaf(ar[r], bc[c], sacc[r][c]);
        }

        // Online softmax (reduction across the 16 tx lanes of each row group)
#pragma unroll
        for (int r = 0; r < 4; r++) {
#pragma unroll
            for (int c = 0; c < 4; c++) sacc[r][c] *= SCALE_;
            float mx = fmaxf(fmaxf(sacc[r][0], sacc[r][1]), fmaxf(sacc[r][2], sacc[r][3]));
#pragma unroll
            for (int o = 8; o >= 1; o >>= 1) mx = fmaxf(mx, __shfl_xor_sync(0xffffffffu, mx, o));
            float mn = fmaxf(m_old[r], mx);
            float alpha = __expf(m_old[r] - mn);
            float ssum = 0.f;
#pragma unroll
            for (int c = 0; c < 4; c++) {
                float pv = __expf(sacc[r][c] - mn);
                sacc[r][c] = pv;
                ssum += pv;
            }
#pragma unroll
            for (int o = 8; o >= 1; o >>= 1) ssum += __shfl_xor_sync(0xffffffffu, ssum, o);
            lsum[r] = lsum[r] * alpha + ssum;
            m_old[r] = mn;
#pragma unroll
            for (int c = 0; c < 4; c++) O[r][c] *= alpha;
            *(float4*)&Ps[(ty * 4 + r) * PADW + tx * 4] =
                make_float4(sacc[r][0], sacc[r][1], sacc[r][2], sacc[r][3]);
        }
        __syncthreads();

        // O += P V
#pragma unroll
        for (int jj = 0; jj < 64; jj++) {
            float a0 = Ps[(ty * 4 + 0) * PADW + jj];
            float a1 = Ps[(ty * 4 + 1) * PADW + jj];
            float a2 = Ps[(ty * 4 + 2) * PADW + jj];
            float a3 = Ps[(ty * 4 + 3) * PADW + jj];
            float4 v4 = *(const float4*)&Vs[jj * PADW + tx * 4];
            float vc[4] = {v4.x, v4.y, v4.z, v4.w};
#pragma unroll
            for (int c = 0; c < 4; c++) {
                O[0][c] = fmaf(a0, vc[c], O[0][c]);
                O[1][c] = fmaf(a1, vc[c], O[1][c]);
                O[2][c] = fmaf(a2, vc[c], O[2][c]);
                O[3][c] = fmaf(a3, vc[c], O[3][c]);
            }
        }
    }

    // Normalize and store [b][s][h*64+d]
    float* ob = g_ao + (size_t)b * S_ * C_;
#pragma unroll
    for (int r = 0; r < 4; r++) {
        float inv = 1.f / lsum[r];
        float4 v;
        v.x = O[r][0] * inv; v.y = O[r][1] * inv;
        v.z = O[r][2] * inv; v.w = O[r][3] * inv;
        *(float4*)&ob[(size_t)(i0 + ty * 4 + r) * C_ + h * 64 + tx * 4] = v;
    }
}

// ---------------------------------------------------------------------------
// Kernel 3: out = g_ao @ w_out + b_out + x, written transposed to [b][c][s].
// A(m,k) = g_ao[b][m*256+k] (row-major), B(k,n) = w_out[k*256+n]
// ---------------------------------------------------------------------------
__global__ void __launch_bounds__(256) out_gemm_kernel(const float* __restrict__ wo,
                                                       const float* __restrict__ bo,
                                                       const float* __restrict__ x,
                                                       float* __restrict__ out) {
    __shared__ float As[8][132];
    __shared__ float Bs[8][132];

    const int b  = blockIdx.z;
    const int m0 = blockIdx.y * 128;
    const int n0 = blockIdx.x * 128;
    const float* ab = g_ao + (size_t)b * S_ * C_;

    const int tid = threadIdx.x;
    const int tx = tid & 15, ty = tid >> 4;

    float acc[8][8];
#pragma unroll
    for (int r = 0; r < 8; r++)
#pragma unroll
        for (int c = 0; c < 8; c++) acc[r][c] = 0.f;

    const int a_kk = tid & 7, a_mmb = tid >> 3;    // A loader: k contiguous (8 wide)
    const int b_nn = tid & 127, b_k2 = tid >> 7;

    for (int k0 = 0; k0 < C_; k0 += 8) {
#pragma unroll
        for (int p = 0; p < 4; p++) {
            int mm = a_mmb + p * 32;
            As[a_kk][mm] = ab[(size_t)(m0 + mm) * C_ + k0 + a_kk];
        }
#pragma unroll
        for (int p = 0; p < 4; p++) {
            int kk = b_k2 + p * 2;
            Bs[kk][b_nn] = wo[(size_t)(k0 + kk) * C_ + n0 + b_nn];
        }
        __syncthreads();

#pragma unroll
        for (int kk = 0; kk < 8; kk++) {
            float a[8], bb[8];
            *(float4*)(a)     = *(const float4*)&As[kk][ty * 8];
            *(float4*)(a + 4) = *(const float4*)&As[kk][ty * 8 + 4];
            *(float4*)(bb)     = *(const float4*)&Bs[kk][tx * 8];
            *(float4*)(bb + 4) = *(const float4*)&Bs[kk][tx * 8 + 4];
#pragma unroll
            for (int r = 0; r < 8; r++)
#pragma unroll
                for (int c = 0; c < 8; c++) acc[r][c] = fmaf(a[r], bb[c], acc[r][c]);
        }
        __syncthreads();
    }

    // Epilogue: + b_out[ch] + x[b,ch,m], write out[b][ch][m] (transposed)
    const float* xb = x + (size_t)b * C_ * S_;
    float* ob = out + (size_t)b * C_ * S_;
    const int m = m0 + ty * 8;
#pragma unroll
    for (int c = 0; c < 8; c++) {
        const int ch = n0 + tx * 8 + c;
        const float bias = bo[ch];
        const float* xr = &xb[(size_t)ch * S_ + m];
        float*       orow = &ob[(size_t)ch * S_ + m];
        float4 x0 = *(const float4*)(xr);
        float4 x1 = *(const float4*)(xr + 4);
        float4 v0, v1;
        v0.x = acc[0][c] + bias + x0.x; v0.y = acc[1][c] + bias + x0.y;
        v0.z = acc[2][c] + bias + x0.z; v0.w = acc[3][c] + bias + x0.w;
        v1.x = acc[4][c] + bias + x1.x; v1.y = acc[5][c] + bias + x1.y;
        v1.z = acc[6][c] + bias + x1.z; v1.w = acc[7][c] + bias + x1.w;
        *(float4*)(orow)     = v0;
        *(float4*)(orow + 4) = v1;
    }
}

// ---------------------------------------------------------------------------
extern "C" void kernel_launch(void* const* d_in, const int* in_sizes, int n_in,
                              void* d_out, int out_size) {
    const float* x  = (const float*)d_in[0];
    const float* wp = (const float*)d_in[1];
    const float* bp = (const float*)d_in[2];
    const float* wo = (const float*)d_in[3];
    const float* bo = (const float*)d_in[4];
    float* out = (float*)d_out;

    // 1) QKV projection
    qkv_gemm_kernel<<<dim3(O3_ / 128, S_ / 128, B_), 256>>>(x, wp, bp);

    // 2) attention (needs >48KB dynamic smem)
    const size_t smem = 4 * 64 * PADW * sizeof(float);   // 69632 B
    static int smem_set = 0;
    if (!smem_set) {
        cudaFuncSetAttribute(attn_kernel, cudaFuncAttributeMaxDynamicSharedMemorySize, (int)smem);
        smem_set = 1;
    }
    attn_kernel<<<dim3(S_ / 64, H_, B_), 256, smem>>>();

    // 3) out projection + bias + residual + transpose
    out_gemm_kernel<<<dim3(C_ / 128, S_ / 128, B_), 256>>>(wo, bo, x, out);
}

// round 2
// speedup vs baseline: 2.1670x; 2.1670x over previous
#include <cuda_runtime.h>
#include <cuda_bf16.h>
#include <math.h>

// Problem constants
#define B_   16
#define C_   256
#define S_   1024
#define H_   4
#define D_   64
#define O3_  768
#define SCALE_ 0.125f
#define LOG2E_ 1.4426950408889634f

// Scratch
__device__ float g_qkv[B_ * S_ * O3_];   // [b][s][768]  o = h*192 + {q:0..63,k:64..127,v:128..191}
__device__ float g_ao [B_ * S_ * C_];    // [b][s][256]  (h*64+d)

// ---------------------------------------------------------------------------
// helpers
// ---------------------------------------------------------------------------
__device__ __forceinline__ unsigned f2tf(float x) {
    unsigned u; asm("cvt.rna.tf32.f32 %0, %1;" : "=r"(u) : "f"(x)); return u;
}
__device__ __forceinline__ float tf32r(float x) {
    unsigned u; asm("cvt.rna.tf32.f32 %0, %1;" : "=r"(u) : "f"(x));
    return __uint_as_float(u);
}
__device__ __forceinline__ void mma8(float c[4], const unsigned a[4], const unsigned b[2]) {
    asm volatile("mma.sync.aligned.m16n8k8.row.col.f32.tf32.tf32.f32 "
                 "{%0,%1,%2,%3},{%4,%5,%6,%7},{%8,%9},{%0,%1,%2,%3};"
                 : "+f"(c[0]), "+f"(c[1]), "+f"(c[2]), "+f"(c[3])
                 : "r"(a[0]), "r"(a[1]), "r"(a[2]), "r"(a[3]),
                   "r"(b[0]), "r"(b[1]));
}
// Fast exp2 on the FMA/ALU pipes (avoids the MUFU throughput wall).
// Valid for x <= 0 (softmax arguments); clamped at -126 to avoid exponent wrap.
__device__ __forceinline__ float exp2fast(float x) {
    x = fmaxf(x, -126.0f);
    float z = x + 12582912.0f;            // 1.5*2^23: round-to-nearest-int
    int   n = __float_as_int(z) - 0x4B400000;
    float f = x - (z - 12582912.0f);      // f in [-0.5, 0.5]
    float p = 0.0013333558f;
    p = fmaf(p, f, 0.0096181291f);
    p = fmaf(p, f, 0.0555041087f);
    p = fmaf(p, f, 0.2402265070f);
    p = fmaf(p, f, 0.6931471806f);
    p = fmaf(p, f, 1.0f);
    return __int_as_float(__float_as_int(p) + (n << 23));
}

// ---------------------------------------------------------------------------
// Kernel 1: QKV projection (tf32 mma). qkv[b,s,o] = x[b,:,s]^T @ w_proj + b_proj
// CTA 128x128, K-chunk 32. 8 warps, warp tile 32x64 (2 m16 x 8 n8).
// ---------------------------------------------------------------------------
__global__ void __launch_bounds__(256, 2) qkv_gemm(const float* __restrict__ x,
                                                   const float* __restrict__ wp,
                                                   const float* __restrict__ bp) {
    __shared__ float As[32][132];   // [k][m]
    __shared__ float Bs[32][132];   // [k][n]
    const int b  = blockIdx.z;
    const int m0 = blockIdx.y * 128;
    const int n0 = blockIdx.x * 128;
    const int tid = threadIdx.x, warp = tid >> 5, lane = tid & 31;
    const int g = lane >> 2, t = lane & 3;
    const int wm = (warp >> 1) * 32, wn = (warp & 1) * 64;
    const float* xb = x + (size_t)b * C_ * S_;

    float acc[2][8][4];
#pragma unroll
    for (int mt = 0; mt < 2; mt++)
#pragma unroll
        for (int nt = 0; nt < 8; nt++)
#pragma unroll
            for (int i = 0; i < 4; i++) acc[mt][nt][i] = 0.f;

    for (int k0 = 0; k0 < C_; k0 += 32) {
#pragma unroll
        for (int p = 0; p < 4; p++) {
            int idx = tid + p * 256;
            int kk = idx >> 5, c4 = (idx & 31) * 4;
            float4 v = *(const float4*)&xb[(size_t)(k0 + kk) * S_ + m0 + c4];
            As[kk][c4 + 0] = tf32r(v.x); As[kk][c4 + 1] = tf32r(v.y);
            As[kk][c4 + 2] = tf32r(v.z); As[kk][c4 + 3] = tf32r(v.w);
        }
#pragma unroll
        for (int p = 0; p < 4; p++) {
            int idx = tid + p * 256;
            int kk = idx >> 5, c4 = (idx & 31) * 4;
            float4 v = *(const float4*)&wp[(size_t)(k0 + kk) * O3_ + n0 + c4];
            Bs[kk][c4 + 0] = tf32r(v.x); Bs[kk][c4 + 1] = tf32r(v.y);
            Bs[kk][c4 + 2] = tf32r(v.z); Bs[kk][c4 + 3] = tf32r(v.w);
        }
        __syncthreads();
#pragma unroll
        for (int ks = 0; ks < 4; ks++) {
            const int kb = ks * 8;
            unsigned a[2][4], bb[8][2];
#pragma unroll
            for (int mt = 0; mt < 2; mt++) {
                int m = wm + mt * 16 + g;
                a[mt][0] = __float_as_uint(As[kb + t][m]);
                a[mt][1] = __float_as_uint(As[kb + t][m + 8]);
                a[mt][2] = __float_as_uint(As[kb + t + 4][m]);
                a[mt][3] = __float_as_uint(As[kb + t + 4][m + 8]);
            }
#pragma unroll
            for (int nt = 0; nt < 8; nt++) {
                int n = wn + nt * 8 + g;
                bb[nt][0] = __float_as_uint(Bs[kb + t][n]);
                bb[nt][1] = __float_as_uint(Bs[kb + t + 4][n]);
            }
#pragma unroll
            for (int mt = 0; mt < 2; mt++)
#pragma unroll
                for (int nt = 0; nt < 8; nt++) mma8(acc[mt][nt], a[mt], bb[nt]);
        }
        __syncthreads();
    }

    float* qb = g_qkv + (size_t)b * S_ * O3_;
#pragma unroll
    for (int mt = 0; mt < 2; mt++) {
        const int r1 = m0 + wm + mt * 16 + g, r2 = r1 + 8;
#pragma unroll
        for (int nt = 0; nt < 8; nt++) {
            const int cn = n0 + wn + nt * 8 + 2 * t;
            const float b0 = bp[cn], b1 = bp[cn + 1];
            *(float2*)&qb[(size_t)r1 * O3_ + cn] =
                make_float2(acc[mt][nt][0] + b0, acc[mt][nt][1] + b1);
            *(float2*)&qb[(size_t)r2 * O3_ + cn] =
                make_float2(acc[mt][nt][2] + b0, acc[mt][nt][3] + b1);
        }
    }
}

// ---------------------------------------------------------------------------
// Kernel 2: flash attention (tf32 mma + FMA-pipe exp2).
// CTA per (b, h, 128-row i-tile). 8 warps, each owns 16 rows.
// Q fragments live in registers; K/V/P staged in smem.
// ---------------------------------------------------------------------------
#define PW 68
__global__ void __launch_bounds__(256, 1) attn_kernel() {
    extern __shared__ float sm[];
    float* Ks = sm;                // [64][PW]  (j, d)
    float* Vs = sm + 64 * PW;      // [64][PW]  (j, d)
    float* Ps = sm + 128 * PW;     // [128][PW] (i, j)

    const int i0 = blockIdx.x * 128;
    const int h  = blockIdx.y;
    const int b  = blockIdx.z;
    const float* qkv = g_qkv + (size_t)b * S_ * O3_;

    const int tid = threadIdx.x, warp = tid >> 5, lane = tid & 31;
    const int g = lane >> 2, t = lane & 3;

    // Q fragments, scale*log2e folded in (softmax done in base 2)
    unsigned qa[8][4];
    {
        const float sc = SCALE_ * LOG2E_;
        const float* q1 = qkv + (size_t)(i0 + warp * 16 + g) * O3_ + h * 192;
        const float* q2 = q1 + 8 * O3_;
#pragma unroll
        for (int ks = 0; ks < 8; ks++) {
            qa[ks][0] = f2tf(q1[ks * 8 + t] * sc);
            qa[ks][1] = f2tf(q2[ks * 8 + t] * sc);
            qa[ks][2] = f2tf(q1[ks * 8 + t + 4] * sc);
            qa[ks][3] = f2tf(q2[ks * 8 + t + 4] * sc);
        }
    }

    float oacc[8][4];
#pragma unroll
    for (int nt = 0; nt < 8; nt++)
#pragma unroll
        for (int i = 0; i < 4; i++) oacc[nt][i] = 0.f;
    float m1 = -1e30f, m2 = -1e30f, l1 = 0.f, l2 = 0.f;

    float* pr1 = &Ps[(warp * 16 + g) * PW];
    float* pr2 = pr1 + 8 * PW;

    for (int jt = 0; jt < 16; jt++) {
        __syncthreads();   // previous PV done before K/V overwrite
        const int j0 = jt * 64;
#pragma unroll
        for (int p = 0; p < 4; p++) {
            int idx = tid + p * 256;
            int j = idx >> 4, c4 = (idx & 15) * 4;
            const float* base = &qkv[(size_t)(j0 + j) * O3_ + h * 192];
            float4 kv = *(const float4*)&base[64 + c4];
            Ks[j * PW + c4 + 0] = tf32r(kv.x); Ks[j * PW + c4 + 1] = tf32r(kv.y);
            Ks[j * PW + c4 + 2] = tf32r(kv.z); Ks[j * PW + c4 + 3] = tf32r(kv.w);
            float4 vv = *(const float4*)&base[128 + c4];
            Vs[j * PW + c4 + 0] = tf32r(vv.x); Vs[j * PW + c4 + 1] = tf32r(vv.y);
            Vs[j * PW + c4 + 2] = tf32r(vv.z); Vs[j * PW + c4 + 3] = tf32r(vv.w);
        }
        __syncthreads();

        // S = Q K^T (in log2 units)
        float sacc[8][4];
#pragma unroll
        for (int nt = 0; nt < 8; nt++)
#pragma unroll
            for (int i = 0; i < 4; i++) sacc[nt][i] = 0.f;
#pragma unroll
        for (int ks = 0; ks < 8; ks++) {
            const int kb = ks * 8;
#pragma unroll
            for (int nt = 0; nt < 8; nt++) {
                unsigned bb[2];
                bb[0] = __float_as_uint(Ks[(nt * 8 + g) * PW + kb + t]);
                bb[1] = __float_as_uint(Ks[(nt * 8 + g) * PW + kb + t + 4]);
                mma8(sacc[nt], qa[ks], bb);
            }
        }

        // online softmax (rows g and g+8 of this warp's 16)
        float mx1 = -1e30f, mx2 = -1e30f;
#pragma unroll
        for (int nt = 0; nt < 8; nt++) {
            mx1 = fmaxf(mx1, fmaxf(sacc[nt][0], sacc[nt][1]));
            mx2 = fmaxf(mx2, fmaxf(sacc[nt][2], sacc[nt][3]));
        }
        mx1 = fmaxf(mx1, __shfl_xor_sync(0xffffffffu, mx1, 1));
        mx1 = fmaxf(mx1, __shfl_xor_sync(0xffffffffu, mx1, 2));
        mx2 = fmaxf(mx2, __shfl_xor_sync(0xffffffffu, mx2, 1));
        mx2 = fmaxf(mx2, __shfl_xor_sync(0xffffffffu, mx2, 2));
        const float mn1 = fmaxf(m1, mx1), mn2 = fmaxf(m2, mx2);
        const float al1 = exp2fast(m1 - mn1), al2 = exp2fast(m2 - mn2);
        m1 = mn1; m2 = mn2;

        float s1 = 0.f, s2 = 0.f;
#pragma unroll
        for (int nt = 0; nt < 8; nt++) {
            float p0 = exp2fast(sacc[nt][0] - mn1);
            float p1 = exp2fast(sacc[nt][1] - mn1);
            float p2 = exp2fast(sacc[nt][2] - mn2);
            float p3 = exp2fast(sacc[nt][3] - mn2);
            s1 += p0 + p1; s2 += p2 + p3;
            *(float2*)&pr1[nt * 8 + 2 * t] = make_float2(tf32r(p0), tf32r(p1));
            *(float2*)&pr2[nt * 8 + 2 * t] = make_float2(tf32r(p2), tf32r(p3));
            oacc[nt][0] *= al1; oacc[nt][1] *= al1;
            oacc[nt][2] *= al2; oacc[nt][3] *= al2;
        }
        s1 += __shfl_xor_sync(0xffffffffu, s1, 1);
        s1 += __shfl_xor_sync(0xffffffffu, s1, 2);
        s2 += __shfl_xor_sync(0xffffffffu, s2, 1);
        s2 += __shfl_xor_sync(0xffffffffu, s2, 2);
        l1 = l1 * al1 + s1;
        l2 = l2 * al2 + s2;
        __syncwarp();   // P smem visible within warp

        // O += P V
#pragma unroll
        for (int ks = 0; ks < 8; ks++) {
            const int kb = ks * 8;
            unsigned pa[4];
            pa[0] = __float_as_uint(pr1[kb + t]);
            pa[1] = __float_as_uint(pr2[kb + t]);
            pa[2] = __float_as_uint(pr1[kb + t + 4]);
            pa[3] = __float_as_uint(pr2[kb + t + 4]);
#pragma unroll
            for (int nt = 0; nt < 8; nt++) {
                unsigned vb[2];
                vb[0] = __float_as_uint(Vs[(kb + t) * PW + nt * 8 + g]);
                vb[1] = __float_as_uint(Vs[(kb + t + 4) * PW + nt * 8 + g]);
                mma8(oacc[nt], pa, vb);
            }
        }
    }

    // normalize + store
    const float inv1 = 1.f / l1, inv2 = 1.f / l2;
    float* ob1 = g_ao + (size_t)b * S_ * C_ + (size_t)(i0 + warp * 16 + g) * C_ + h * 64;
    float* ob2 = ob1 + 8 * C_;
#pragma unroll
    for (int nt = 0; nt < 8; nt++) {
        *(float2*)&ob1[nt * 8 + 2 * t] =
            make_float2(oacc[nt][0] * inv1, oacc[nt][1] * inv1);
        *(float2*)&ob2[nt * 8 + 2 * t] =
            make_float2(oacc[nt][2] * inv2, oacc[nt][3] * inv2);
    }
}

// ---------------------------------------------------------------------------
// Kernel 3: out = g_ao @ w_out + b_out + x, stored transposed [b][c][s].
// ---------------------------------------------------------------------------
__global__ void __launch_bounds__(256, 2) out_gemm(const float* __restrict__ wo,
                                                   const float* __restrict__ bo,
                                                   const float* __restrict__ x,
                                                   float* __restrict__ out) {
    __shared__ float As[128][36];   // [m][k]
    __shared__ float Bs[32][132];   // [k][n]
    const int b  = blockIdx.z;
    const int m0 = blockIdx.y * 128;
    const int n0 = blockIdx.x * 128;
    const int tid = threadIdx.x, warp = tid >> 5, lane = tid & 31;
    const int g = lane >> 2, t = lane & 3;
    const int wm = (warp >> 1) * 32, wn = (warp & 1) * 64;
    const float* ab = g_ao + (size_t)b * S_ * C_;

    float acc[2][8][4];
#pragma unroll
    for (int mt = 0; mt < 2; mt++)
#pragma unroll
        for (int nt = 0; nt < 8; nt++)
#pragma unroll
            for (int i = 0; i < 4; i++) acc[mt][nt][i] = 0.f;

    for (int k0 = 0; k0 < C_; k0 += 32) {
#pragma unroll
        for (int p = 0; p < 4; p++) {
            int idx = tid + p * 256;
            int m = idx >> 3, c4 = (idx & 7) * 4;
            float4 v = *(const float4*)&ab[(size_t)(m0 + m) * C_ + k0 + c4];
            As[m][c4 + 0] = tf32r(v.x); As[m][c4 + 1] = tf32r(v.y);
            As[m][c4 + 2] = tf32r(v.z); As[m][c4 + 3] = tf32r(v.w);
        }
#pragma unroll
        for (int p = 0; p < 4; p++) {
            int idx = tid + p * 256;
            int kk = idx >> 5, c4 = (idx & 31) * 4;
            float4 v = *(const float4*)&wo[(size_t)(k0 + kk) * C_ + n0 + c4];
            Bs[kk][c4 + 0] = tf32r(v.x); Bs[kk][c4 + 1] = tf32r(v.y);
            Bs[kk][c4 + 2] = tf32r(v.z); Bs[kk][c4 + 3] = tf32r(v.w);
        }
        __syncthreads();
#pragma unroll
        for (int ks = 0; ks < 4; ks++) {
            const int kb = ks * 8;
            unsigned a[2][4], bb[8][2];
#pragma unroll
            for (int mt = 0; mt < 2; mt++) {
                int m = wm + mt * 16 + g;
                a[mt][0] = __float_as_uint(As[m][kb + t]);
                a[mt][1] = __float_as_uint(As[m + 8][kb + t]);
                a[mt][2] = __float_as_uint(As[m][kb + t + 4]);
                a[mt][3] = __float_as_uint(As[m + 8][kb + t + 4]);
            }
#pragma unroll
            for (int nt = 0; nt < 8; nt++) {
                int n = wn + nt * 8 + g;
                bb[nt][0] = __float_as_uint(Bs[kb + t][n]);
                bb[nt][1] = __float_as_uint(Bs[kb + t + 4][n]);
            }
#pragma unroll
            for (int mt = 0; mt < 2; mt++)
#pragma unroll
                for (int nt = 0; nt < 8; nt++) mma8(acc[mt][nt], a[mt], bb[nt]);
        }
        __syncthreads();
    }

    // epilogue: + bias + residual, transposed store out[b][ch][m]
    const float* xb = x + (size_t)b * C_ * S_;
    float* ob = out + (size_t)b * C_ * S_;
#pragma unroll
    for (int mt = 0; mt < 2; mt++) {
        const int r1 = m0 + wm + mt * 16 + g, r2 = r1 + 8;
#pragma unroll
        for (int nt = 0; nt < 8; nt++) {
            const int c0 = n0 + wn + nt * 8 + 2 * t, c1 = c0 + 1;
            const float bo0 = bo[c0], bo1 = bo[c1];
            ob[(size_t)c0 * S_ + r1] = acc[mt][nt][0] + bo0 + xb[(size_t)c0 * S_ + r1];
            ob[(size_t)c1 * S_ + r1] = acc[mt][nt][1] + bo1 + xb[(size_t)c1 * S_ + r1];
            ob[(size_t)c0 * S_ + r2] = acc[mt][nt][2] + bo0 + xb[(size_t)c0 * S_ + r2];
            ob[(size_t)c1 * S_ + r2] = acc[mt][nt][3] + bo1 + xb[(size_t)c1 * S_ + r2];
        }
    }
}

// ---------------------------------------------------------------------------
extern "C" void kernel_launch(void* const* d_in, const int* in_sizes, int n_in,
                              void* d_out, int out_size) {
    const float* x  = (const float*)d_in[0];
    const float* wp = (const float*)d_in[1];
    const float* bp = (const float*)d_in[2];
    const float* wo = (const float*)d_in[3];
    const float* bo = (const float*)d_in[4];
    float* out = (float*)d_out;

    qkv_gemm<<<dim3(O3_ / 128, S_ / 128, B_), 256>>>(x, wp, bp);

    const size_t smem = 256 * PW * sizeof(float);   // 69632 B
    static int smem_set = 0;
    if (!smem_set) {
        cudaFuncSetAttribute(attn_kernel, cudaFuncAttributeMaxDynamicSharedMemorySize, (int)smem);
        smem_set = 1;
    }
    attn_kernel<<<dim3(S_ / 128, H_, B_), 256, smem>>>();

    out_gemm<<<dim3(C_ / 128, S_ / 128, B_), 256>>>(wo, bo, x, out);
}

// round 3
// speedup vs baseline: 4.7106x; 2.1738x over previous
#include <cuda_runtime.h>
#include <cuda_bf16.h>

#define B_   16
#define C_   256
#define S_   1024
#define H_   4
#define O3_  768
#define SCALE_ 0.125f
#define LOG2E_ 1.4426950408889634f

// bf16 intermediates
__device__ __align__(16) __nv_bfloat16 g_qkvh[B_ * S_ * O3_];  // [b][s][768], o=h*192+{q,k,v}
__device__ __align__(16) __nv_bfloat16 g_aoh [B_ * S_ * C_];   // [b][s][256]

// ---------------------------------------------------------------------------
// helpers
// ---------------------------------------------------------------------------
__device__ __forceinline__ unsigned smem_u32(const void* p) {
    return (unsigned)__cvta_generic_to_shared(p);
}
__device__ __forceinline__ void ldsm4(unsigned& r0, unsigned& r1, unsigned& r2, unsigned& r3,
                                      unsigned a) {
    asm volatile("ldmatrix.sync.aligned.m8n8.x4.shared.b16 {%0,%1,%2,%3},[%4];"
                 : "=r"(r0), "=r"(r1), "=r"(r2), "=r"(r3) : "r"(a));
}
__device__ __forceinline__ void ldsm4t(unsigned& r0, unsigned& r1, unsigned& r2, unsigned& r3,
                                       unsigned a) {
    asm volatile("ldmatrix.sync.aligned.m8n8.x4.trans.shared.b16 {%0,%1,%2,%3},[%4];"
                 : "=r"(r0), "=r"(r1), "=r"(r2), "=r"(r3) : "r"(a));
}
__device__ __forceinline__ void mma16(float c[4], const unsigned a[4], const unsigned b[2]) {
    asm volatile("mma.sync.aligned.m16n8k16.row.col.f32.bf16.bf16.f32 "
                 "{%0,%1,%2,%3},{%4,%5,%6,%7},{%8,%9},{%0,%1,%2,%3};"
                 : "+f"(c[0]), "+f"(c[1]), "+f"(c[2]), "+f"(c[3])
                 : "r"(a[0]), "r"(a[1]), "r"(a[2]), "r"(a[3]),
                   "r"(b[0]), "r"(b[1]));
}
#define CP16(dst, src) \
    asm volatile("cp.async.cg.shared.global [%0], [%1], 16;" :: "r"(dst), "l"(src))
#define CPCOMMIT() asm volatile("cp.async.commit_group;")
#define CPWAIT0()  asm volatile("cp.async.wait_group 0;")

__device__ __forceinline__ unsigned packbf(float lo, float hi) {
    __nv_bfloat162 v = __floats2bfloat162_rn(lo, hi);  // .x = lo (low 16 bits)
    return *(unsigned*)&v;
}
// FMA-pipe exp2 (x <= 0)
__device__ __forceinline__ float exp2fast(float x) {
    x = fmaxf(x, -126.0f);
    float z = x + 12582912.0f;
    int   n = __float_as_int(z) - 0x4B400000;
    float f = x - (z - 12582912.0f);
    float p = 0.0013333558f;
    p = fmaf(p, f, 0.0096181291f);
    p = fmaf(p, f, 0.0555041087f);
    p = fmaf(p, f, 0.2402265070f);
    p = fmaf(p, f, 0.6931471806f);
    p = fmaf(p, f, 1.0f);
    return __int_as_float(__float_as_int(p) + (n << 23));
}

// ---------------------------------------------------------------------------
// Kernel 1: QKV projection. A = x^T (smem [k][m]), B = w_proj (smem [k][n]).
// 128x128 CTA tile, k-chunk 32, 8 warps (warp tile 32x64), bf16 MMA + LDSM.
// ---------------------------------------------------------------------------
__global__ void __launch_bounds__(256, 2) qkv_gemm(const float* __restrict__ x,
                                                   const float* __restrict__ wp,
                                                   const float* __restrict__ bp) {
    __shared__ __align__(16) __nv_bfloat16 As[32][136];   // [k][m], stride 272B
    __shared__ __align__(16) __nv_bfloat16 Bs[32][136];   // [k][n]
    const int b  = blockIdx.z;
    const int m0 = blockIdx.y * 128;
    const int n0 = blockIdx.x * 128;
    const int tid = threadIdx.x, warp = tid >> 5, lane = tid & 31;
    const int t = lane & 3;
    const int wm = (warp >> 1) * 32, wn = (warp & 1) * 64;
    const float* xb = x + (size_t)b * C_ * S_;
    const unsigned as_b = smem_u32(&As[0][0]), bs_b = smem_u32(&Bs[0][0]);
    const int l7 = lane & 7, lq1 = (lane >> 3) & 1, lq2 = (lane >> 4) & 1;

    float acc[2][8][4];
#pragma unroll
    for (int mt = 0; mt < 2; mt++)
#pragma unroll
        for (int nt = 0; nt < 8; nt++)
#pragma unroll
            for (int i = 0; i < 4; i++) acc[mt][nt][i] = 0.f;

    for (int k0 = 0; k0 < C_; k0 += 32) {
#pragma unroll
        for (int p = 0; p < 4; p++) {
            int idx = tid + p * 256;
            int kk = idx >> 5, c4 = (idx & 31) * 4;
            float4 v = *(const float4*)&xb[(size_t)(k0 + kk) * S_ + m0 + c4];
            *(__nv_bfloat162*)&As[kk][c4]     = __floats2bfloat162_rn(v.x, v.y);
            *(__nv_bfloat162*)&As[kk][c4 + 2] = __floats2bfloat162_rn(v.z, v.w);
        }
#pragma unroll
        for (int p = 0; p < 4; p++) {
            int idx = tid + p * 256;
            int kk = idx >> 5, c4 = (idx & 31) * 4;
            float4 v = *(const float4*)&wp[(size_t)(k0 + kk) * O3_ + n0 + c4];
            *(__nv_bfloat162*)&Bs[kk][c4]     = __floats2bfloat162_rn(v.x, v.y);
            *(__nv_bfloat162*)&Bs[kk][c4 + 2] = __floats2bfloat162_rn(v.z, v.w);
        }
        __syncthreads();
#pragma unroll
        for (int ks = 0; ks < 2; ks++) {
            const int kb = ks * 16;
            unsigned a[2][4];
#pragma unroll
            for (int mt = 0; mt < 2; mt++)   // trans: [k][m] -> A[m][k]
                ldsm4t(a[mt][0], a[mt][1], a[mt][2], a[mt][3],
                       as_b + ((kb + lq2 * 8 + l7) * 136 + wm + mt * 16 + lq1 * 8) * 2);
#pragma unroll
            for (int np = 0; np < 4; np++) {
                unsigned r0, r1, r2, r3;
                ldsm4t(r0, r1, r2, r3,
                       bs_b + ((kb + lq1 * 8 + l7) * 136 + wn + np * 16 + lq2 * 8) * 2);
                unsigned blo[2] = {r0, r1}, bhi[2] = {r2, r3};
#pragma unroll
                for (int mt = 0; mt < 2; mt++) {
                    mma16(acc[mt][2 * np],     a[mt], blo);
                    mma16(acc[mt][2 * np + 1], a[mt], bhi);
                }
            }
        }
        __syncthreads();
    }

    __nv_bfloat16* qb = g_qkvh + (size_t)b * S_ * O3_;
    const int g = lane >> 2;
#pragma unroll
    for (int mt = 0; mt < 2; mt++) {
        const int r1 = m0 + wm + mt * 16 + g, r2 = r1 + 8;
#pragma unroll
        for (int nt = 0; nt < 8; nt++) {
            const int cn = n0 + wn + nt * 8 + 2 * t;
            const float b0 = bp[cn], b1 = bp[cn + 1];
            *(__nv_bfloat162*)&qb[(size_t)r1 * O3_ + cn] =
                __floats2bfloat162_rn(acc[mt][nt][0] + b0, acc[mt][nt][1] + b1);
            *(__nv_bfloat162*)&qb[(size_t)r2 * O3_ + cn] =
                __floats2bfloat162_rn(acc[mt][nt][2] + b0, acc[mt][nt][3] + b1);
        }
    }
}

// ---------------------------------------------------------------------------
// Kernel 2: flash attention, bf16 MMA, P kept in registers (no smem round-trip).
// CTA per (b, h, 128-row i-tile); 8 warps x 16 rows. K/V tiles via cp.async.
// ---------------------------------------------------------------------------
__global__ void __launch_bounds__(256, 2) attn_kernel() {
    __shared__ __align__(16) __nv_bfloat16 Ks[64][72];   // [j][d], stride 144B
    __shared__ __align__(16) __nv_bfloat16 Vs[64][72];   // [j][d]
    const int i0 = blockIdx.x * 128;
    const int h  = blockIdx.y;
    const int b  = blockIdx.z;
    const __nv_bfloat16* qkv = g_qkvh + (size_t)b * S_ * O3_;

    const int tid = threadIdx.x, warp = tid >> 5, lane = tid & 31;
    const int g = lane >> 2, t = lane & 3;
    const int l7 = lane & 7, lq1 = (lane >> 3) & 1, lq2 = (lane >> 4) & 1;
    const unsigned ks_b = smem_u32(&Ks[0][0]), vs_b = smem_u32(&Vs[0][0]);
    const float k2 = SCALE_ * LOG2E_;

    // Q fragments from global (raw bf16; scaling folded into exp args)
    unsigned qa[4][4];
    {
        const __nv_bfloat16* q1 = qkv + (size_t)(i0 + warp * 16 + g) * O3_ + h * 192;
        const __nv_bfloat16* q2 = q1 + 8 * O3_;
#pragma unroll
        for (int c = 0; c < 4; c++) {
            qa[c][0] = *(const unsigned*)&q1[c * 16 + 2 * t];
            qa[c][1] = *(const unsigned*)&q2[c * 16 + 2 * t];
            qa[c][2] = *(const unsigned*)&q1[c * 16 + 8 + 2 * t];
            qa[c][3] = *(const unsigned*)&q2[c * 16 + 8 + 2 * t];
        }
    }

    float oacc[8][4];
#pragma unroll
    for (int nt = 0; nt < 8; nt++)
#pragma unroll
        for (int i = 0; i < 4; i++) oacc[nt][i] = 0.f;
    float m1 = -1e30f, m2 = -1e30f, l1 = 0.f, l2 = 0.f;

    for (int jt = 0; jt < 16; jt++) {
        __syncthreads();   // prior MMAs done before tile overwrite
        {
            const __nv_bfloat16* src = qkv + (size_t)(jt * 64) * O3_ + h * 192 + 64;
#pragma unroll
            for (int p = 0; p < 2; p++) {
                int idx = tid + p * 256;
                int j = idx >> 3, c = idx & 7;
                const __nv_bfloat16* row = src + (size_t)j * O3_ + c * 8;
                CP16(ks_b + j * 144 + c * 16, row);
                CP16(vs_b + j * 144 + c * 16, row + 64);
            }
            CPCOMMIT();
            CPWAIT0();
        }
        __syncthreads();

        // S = Q K^T (raw)
        float sacc[8][4];
#pragma unroll
        for (int nt = 0; nt < 8; nt++)
#pragma unroll
            for (int i = 0; i < 4; i++) sacc[nt][i] = 0.f;
#pragma unroll
        for (int c = 0; c < 4; c++) {
            const int kb = c * 16;
#pragma unroll
            for (int np = 0; np < 4; np++) {
                unsigned r0, r1, r2, r3;   // non-trans: [j][d] -> B frag (k=d,n=j)
                ldsm4(r0, r1, r2, r3,
                      ks_b + ((np * 16 + lq2 * 8 + l7) * 72 + kb + lq1 * 8) * 2);
                unsigned blo[2] = {r0, r1}, bhi[2] = {r2, r3};
                mma16(sacc[2 * np],     qa[c], blo);
                mma16(sacc[2 * np + 1], qa[c], bhi);
            }
        }

        // online softmax (rows g, g+8); scale folded into exp2 argument
        float mx1 = -1e30f, mx2 = -1e30f;
#pragma unroll
        for (int nt = 0; nt < 8; nt++) {
            mx1 = fmaxf(mx1, fmaxf(sacc[nt][0], sacc[nt][1]));
            mx2 = fmaxf(mx2, fmaxf(sacc[nt][2], sacc[nt][3]));
        }
        mx1 = fmaxf(mx1, __shfl_xor_sync(0xffffffffu, mx1, 1));
        mx1 = fmaxf(mx1, __shfl_xor_sync(0xffffffffu, mx1, 2));
        mx2 = fmaxf(mx2, __shfl_xor_sync(0xffffffffu, mx2, 1));
        mx2 = fmaxf(mx2, __shfl_xor_sync(0xffffffffu, mx2, 2));
        const float mn1 = fmaxf(m1, mx1), mn2 = fmaxf(m2, mx2);
        const float al1 = exp2fast((m1 - mn1) * k2), al2 = exp2fast((m2 - mn2) * k2);
        m1 = mn1; m2 = mn2;

        float s1 = 0.f, s2 = 0.f;
        unsigned pa[4][4];
#pragma unroll
        for (int jc = 0; jc < 4; jc++) {
            float p0 = exp2fast((sacc[2 * jc][0] - mn1) * k2);
            float p1 = exp2fast((sacc[2 * jc][1] - mn1) * k2);
            float p2 = exp2fast((sacc[2 * jc][2] - mn2) * k2);
            float p3 = exp2fast((sacc[2 * jc][3] - mn2) * k2);
            float p4 = exp2fast((sacc[2 * jc + 1][0] - mn1) * k2);
            float p5 = exp2fast((sacc[2 * jc + 1][1] - mn1) * k2);
            float p6 = exp2fast((sacc[2 * jc + 1][2] - mn2) * k2);
            float p7 = exp2fast((sacc[2 * jc + 1][3] - mn2) * k2);
            s1 += (p0 + p1) + (p4 + p5);
            s2 += (p2 + p3) + (p6 + p7);
            pa[jc][0] = packbf(p0, p1);
            pa[jc][1] = packbf(p2, p3);
            pa[jc][2] = packbf(p4, p5);
            pa[jc][3] = packbf(p6, p7);
        }
        s1 += __shfl_xor_sync(0xffffffffu, s1, 1);
        s1 += __shfl_xor_sync(0xffffffffu, s1, 2);
        s2 += __shfl_xor_sync(0xffffffffu, s2, 1);
        s2 += __shfl_xor_sync(0xffffffffu, s2, 2);
        l1 = l1 * al1 + s1;
        l2 = l2 * al2 + s2;
#pragma unroll
        for (int nt = 0; nt < 8; nt++) {
            oacc[nt][0] *= al1; oacc[nt][1] *= al1;
            oacc[nt][2] *= al2; oacc[nt][3] *= al2;
        }

        // O += P V  (trans LDSM: [j][d] -> B frag (k=j,n=d))
#pragma unroll
        for (int jc = 0; jc < 4; jc++) {
            const int kc = jc * 16;
#pragma unroll
            for (int dp = 0; dp < 4; dp++) {
                unsigned r0, r1, r2, r3;
                ldsm4t(r0, r1, r2, r3,
                       vs_b + ((kc + lq1 * 8 + l7) * 72 + dp * 16 + lq2 * 8) * 2);
                unsigned blo[2] = {r0, r1}, bhi[2] = {r2, r3};
                mma16(oacc[2 * dp],     pa[jc], blo);
                mma16(oacc[2 * dp + 1], pa[jc], bhi);
            }
        }
    }

    // normalize + bf16 store
    const float inv1 = 1.f / l1, inv2 = 1.f / l2;
    __nv_bfloat16* ob1 = g_aoh + (size_t)b * S_ * C_
                       + (size_t)(i0 + warp * 16 + g) * C_ + h * 64;
    __nv_bfloat16* ob2 = ob1 + 8 * C_;
#pragma unroll
    for (int nt = 0; nt < 8; nt++) {
        *(__nv_bfloat162*)&ob1[nt * 8 + 2 * t] =
            __floats2bfloat162_rn(oacc[nt][0] * inv1, oacc[nt][1] * inv1);
        *(__nv_bfloat162*)&ob2[nt * 8 + 2 * t] =
            __floats2bfloat162_rn(oacc[nt][2] * inv2, oacc[nt][3] * inv2);
    }
}

// ---------------------------------------------------------------------------
// Kernel 3: out = g_aoh @ w_out + b_out + x, stored transposed [b][c][s], fp32.
// A: bf16 [m][k] via cp.async; B: fp32 -> bf16 [k][n].
// ---------------------------------------------------------------------------
__global__ void __launch_bounds__(256, 2) out_gemm(const float* __restrict__ wo,
                                                   const float* __restrict__ bo,
                                                   const float* __restrict__ x,
                                                   float* __restrict__ out) {
    __shared__ __align__(16) __nv_bfloat16 As[128][40];   // [m][k], stride 80B
    __shared__ __align__(16) __nv_bfloat16 Bs[32][136];   // [k][n]
    const int b  = blockIdx.z;
    const int m0 = blockIdx.y * 128;
    const int n0 = blockIdx.x * 128;
    const int tid = threadIdx.x, warp = tid >> 5, lane = tid & 31;
    const int g = lane >> 2, t = lane & 3;
    const int l7 = lane & 7, lq1 = (lane >> 3) & 1, lq2 = (lane >> 4) & 1;
    const int wm = (warp >> 1) * 32, wn = (warp & 1) * 64;
    const __nv_bfloat16* ab = g_aoh + (size_t)b * S_ * C_;
    const unsigned as_b = smem_u32(&As[0][0]), bs_b = smem_u32(&Bs[0][0]);

    float acc[2][8][4];
#pragma unroll
    for (int mt = 0; mt < 2; mt++)
#pragma unroll
        for (int nt = 0; nt < 8; nt++)
#pragma unroll
            for (int i = 0; i < 4; i++) acc[mt][nt][i] = 0.f;

    for (int k0 = 0; k0 < C_; k0 += 32) {
        __syncthreads();
#pragma unroll
        for (int p = 0; p < 2; p++) {
            int idx = tid + p * 256;
            int m = idx >> 2, c = idx & 3;
            CP16(as_b + m * 80 + c * 16, ab + (size_t)(m0 + m) * C_ + k0 + c * 8);
        }
#pragma unroll
        for (int p = 0; p < 4; p++) {
            int idx = tid + p * 256;
            int kk = idx >> 5, c4 = (idx & 31) * 4;
            float4 v = *(const float4*)&wo[(size_t)(k0 + kk) * C_ + n0 + c4];
            *(__nv_bfloat162*)&Bs[kk][c4]     = __floats2bfloat162_rn(v.x, v.y);
            *(__nv_bfloat162*)&Bs[kk][c4 + 2] = __floats2bfloat162_rn(v.z, v.w);
        }
        CPCOMMIT();
        CPWAIT0();
        __syncthreads();
#pragma unroll
        for (int ks = 0; ks < 2; ks++) {
            const int kb = ks * 16;
            unsigned a[2][4];
#pragma unroll
            for (int mt = 0; mt < 2; mt++)   // non-trans: [m][k] A frags
                ldsm4(a[mt][0], a[mt][1], a[mt][2], a[mt][3],
                      as_b + ((wm + mt * 16 + lq1 * 8 + l7) * 40 + kb + lq2 * 8) * 2);
#pragma unroll
            for (int np = 0; np < 4; np++) {
                unsigned r0, r1, r2, r3;
                ldsm4t(r0, r1, r2, r3,
                       bs_b + ((kb + lq1 * 8 + l7) * 136 + wn + np * 16 + lq2 * 8) * 2);
                unsigned blo[2] = {r0, r1}, bhi[2] = {r2, r3};
#pragma unroll
                for (int mt = 0; mt < 2; mt++) {
                    mma16(acc[mt][2 * np],     a[mt], blo);
                    mma16(acc[mt][2 * np + 1], a[mt], bhi);
                }
            }
        }
    }

    // epilogue: + bias + residual (fp32), transposed store out[b][ch][s]
    const float* xb = x + (size_t)b * C_ * S_;
    float* ob = out + (size_t)b * C_ * S_;
#pragma unroll
    for (int mt = 0; mt < 2; mt++) {
        const int r1 = m0 + wm + mt * 16 + g, r2 = r1 + 8;
#pragma unroll
        for (int nt = 0; nt < 8; nt++) {
            const int c0 = n0 + wn + nt * 8 + 2 * t, c1 = c0 + 1;
            const float bo0 = bo[c0], bo1 = bo[c1];
            ob[(size_t)c0 * S_ + r1] = acc[mt][nt][0] + bo0 + xb[(size_t)c0 * S_ + r1];
            ob[(size_t)c1 * S_ + r1] = acc[mt][nt][1] + bo1 + xb[(size_t)c1 * S_ + r1];
            ob[(size_t)c0 * S_ + r2] = acc[mt][nt][2] + bo0 + xb[(size_t)c0 * S_ + r2];
            ob[(size_t)c1 * S_ + r2] = acc[mt][nt][3] + bo1 + xb[(size_t)c1 * S_ + r2];
        }
    }
}

// ---------------------------------------------------------------------------
extern "C" void kernel_launch(void* const* d_in, const int* in_sizes, int n_in,
                              void* d_out, int out_size) {
    const float* x  = (const float*)d_in[0];
    const float* wp = (const float*)d_in[1];
    const float* bp = (const float*)d_in[2];
    const float* wo = (const float*)d_in[3];
    const float* bo = (const float*)d_in[4];
    float* out = (float*)d_out;

    qkv_gemm<<<dim3(O3_ / 128, S_ / 128, B_), 256>>>(x, wp, bp);
    attn_kernel<<<dim3(S_ / 128, H_, B_), 256>>>();
    out_gemm<<<dim3(C_ / 128, S_ / 128, B_), 256>>>(wo, bo, x, out);
}

// round 4
// speedup vs baseline: 4.8998x; 1.0402x over previous
#include <cuda_runtime.h>
#include <cuda_bf16.h>

#define B_   16
#define C_   256
#define S_   1024
#define H_   4
#define O3_  768
#define SCALE_ 0.125f
#define LOG2E_ 1.4426950408889634f

// bf16 intermediates + pre-converted inputs
__device__ __align__(16) __nv_bfloat16 g_qkvh[B_ * S_ * O3_];  // [b][s][768]
__device__ __align__(16) __nv_bfloat16 g_aoh [B_ * S_ * C_];   // [b][s][256]
__device__ __align__(16) __nv_bfloat16 g_xh  [B_ * C_ * S_];   // [b][c][s]
__device__ __align__(16) __nv_bfloat16 g_wph [C_ * O3_];
__device__ __align__(16) __nv_bfloat16 g_woh [C_ * C_];

// ---------------------------------------------------------------------------
__device__ __forceinline__ unsigned smem_u32(const void* p) {
    return (unsigned)__cvta_generic_to_shared(p);
}
__device__ __forceinline__ void ldsm4(unsigned& r0, unsigned& r1, unsigned& r2, unsigned& r3,
                                      unsigned a) {
    asm volatile("ldmatrix.sync.aligned.m8n8.x4.shared.b16 {%0,%1,%2,%3},[%4];"
                 : "=r"(r0), "=r"(r1), "=r"(r2), "=r"(r3) : "r"(a));
}
__device__ __forceinline__ void ldsm4t(unsigned& r0, unsigned& r1, unsigned& r2, unsigned& r3,
                                       unsigned a) {
    asm volatile("ldmatrix.sync.aligned.m8n8.x4.trans.shared.b16 {%0,%1,%2,%3},[%4];"
                 : "=r"(r0), "=r"(r1), "=r"(r2), "=r"(r3) : "r"(a));
}
__device__ __forceinline__ void mma16(float c[4], const unsigned a[4], const unsigned b[2]) {
    asm volatile("mma.sync.aligned.m16n8k16.row.col.f32.bf16.bf16.f32 "
                 "{%0,%1,%2,%3},{%4,%5,%6,%7},{%8,%9},{%0,%1,%2,%3};"
                 : "+f"(c[0]), "+f"(c[1]), "+f"(c[2]), "+f"(c[3])
                 : "r"(a[0]), "r"(a[1]), "r"(a[2]), "r"(a[3]),
                   "r"(b[0]), "r"(b[1]));
}
#define CP16(dst, src) \
    asm volatile("cp.async.cg.shared.global [%0], [%1], 16;" :: "r"(dst), "l"(src))
#define CPCOMMIT() asm volatile("cp.async.commit_group;")
#define CPWAIT0()  asm volatile("cp.async.wait_group 0;")
#define CPWAIT1()  asm volatile("cp.async.wait_group 1;")

__device__ __forceinline__ unsigned packbf(float lo, float hi) {
    __nv_bfloat162 v = __floats2bfloat162_rn(lo, hi);
    return *(unsigned*)&v;
}
__device__ __forceinline__ float exp2fast(float x) {
    x = fmaxf(x, -126.0f);
    float z = x + 12582912.0f;
    int   n = __float_as_int(z) - 0x4B400000;
    float f = x - (z - 12582912.0f);
    float p = 0.0013333558f;
    p = fmaf(p, f, 0.0096181291f);
    p = fmaf(p, f, 0.0555041087f);
    p = fmaf(p, f, 0.2402265070f);
    p = fmaf(p, f, 0.6931471806f);
    p = fmaf(p, f, 1.0f);
    return __int_as_float(__float_as_int(p) + (n << 23));
}

// ---------------------------------------------------------------------------
// Kernel 0: convert x, w_proj, w_out to bf16 (one-shot, elementwise, float4).
// ---------------------------------------------------------------------------
#define NX4  (B_ * C_ * S_ / 4)       // 1048576
#define NWP4 (C_ * O3_ / 4)           // 49152
#define NWO4 (C_ * C_ / 4)            // 16384
__global__ void __launch_bounds__(256) cvt_inputs(const float* __restrict__ x,
                                                  const float* __restrict__ wp,
                                                  const float* __restrict__ wo) {
    int idx = blockIdx.x * 256 + threadIdx.x;
    const int total = NX4 + NWP4 + NWO4;
    if (idx >= total) return;
    const float* src; __nv_bfloat16* dst; int i;
    if (idx < NX4)              { src = x;  dst = g_xh;  i = idx; }
    else if (idx < NX4 + NWP4)  { src = wp; dst = g_wph; i = idx - NX4; }
    else                        { src = wo; dst = g_woh; i = idx - NX4 - NWP4; }
    float4 v = *(const float4*)&src[i * 4];
    *(__nv_bfloat162*)&dst[i * 4]     = __floats2bfloat162_rn(v.x, v.y);
    *(__nv_bfloat162*)&dst[i * 4 + 2] = __floats2bfloat162_rn(v.z, v.w);
}

// ---------------------------------------------------------------------------
// Kernel 1: QKV projection. 128x128 CTA, k-chunk 32, 2-stage cp.async pipeline.
// ---------------------------------------------------------------------------
#define QAS 8704u   // 32*136*2 bytes per A stage
__global__ void __launch_bounds__(256, 2) qkv_gemm(const float* __restrict__ bp) {
    __shared__ __align__(16) __nv_bfloat16 sm[2 * 32 * 136 * 2];  // A[2] then B[2]
    const int b  = blockIdx.z;
    const int m0 = blockIdx.y * 128;
    const int n0 = blockIdx.x * 128;
    const int tid = threadIdx.x, warp = tid >> 5, lane = tid & 31;
    const int t = lane & 3, g = lane >> 2;
    const int wm = (warp >> 1) * 32, wn = (warp & 1) * 64;
    const int l7 = lane & 7, lq1 = (lane >> 3) & 1, lq2 = (lane >> 4) & 1;
    const __nv_bfloat16* xb = g_xh + (size_t)b * C_ * S_;
    const unsigned as_b = smem_u32(sm), bs_b = as_b + 2 * QAS;

    const int lkk = tid >> 4, lc = (tid & 15) * 8;   // loader: row, col8

    float acc[2][8][4];
#pragma unroll
    for (int mt = 0; mt < 2; mt++)
#pragma unroll
        for (int nt = 0; nt < 8; nt++)
#pragma unroll
            for (int i = 0; i < 4; i++) acc[mt][nt][i] = 0.f;

    // issue chunk 0
    {
        CP16(as_b + (lkk * 136 + lc) * 2,        xb + (size_t)lkk * S_ + m0 + lc);
        CP16(as_b + ((lkk + 16) * 136 + lc) * 2, xb + (size_t)(lkk + 16) * S_ + m0 + lc);
        CP16(bs_b + (lkk * 136 + lc) * 2,        g_wph + (size_t)lkk * O3_ + n0 + lc);
        CP16(bs_b + ((lkk + 16) * 136 + lc) * 2, g_wph + (size_t)(lkk + 16) * O3_ + n0 + lc);
        CPCOMMIT();
    }

    for (int it = 0; it < 8; it++) {
        if (it + 1 < 8) {
            const int k0 = (it + 1) * 32;
            const unsigned ao = as_b + ((it + 1) & 1) * QAS;
            const unsigned bo = bs_b + ((it + 1) & 1) * QAS;
            CP16(ao + (lkk * 136 + lc) * 2,        xb + (size_t)(k0 + lkk) * S_ + m0 + lc);
            CP16(ao + ((lkk + 16) * 136 + lc) * 2, xb + (size_t)(k0 + lkk + 16) * S_ + m0 + lc);
            CP16(bo + (lkk * 136 + lc) * 2,        g_wph + (size_t)(k0 + lkk) * O3_ + n0 + lc);
            CP16(bo + ((lkk + 16) * 136 + lc) * 2, g_wph + (size_t)(k0 + lkk + 16) * O3_ + n0 + lc);
            CPCOMMIT();
            CPWAIT1();
        } else {
            CPWAIT0();
        }
        __syncthreads();
        const unsigned ao = as_b + (it & 1) * QAS;
        const unsigned bo = bs_b + (it & 1) * QAS;
#pragma unroll
        for (int ks = 0; ks < 2; ks++) {
            const int kb = ks * 16;
            unsigned a[2][4];
#pragma unroll
            for (int mt = 0; mt < 2; mt++)
                ldsm4t(a[mt][0], a[mt][1], a[mt][2], a[mt][3],
                       ao + ((kb + lq2 * 8 + l7) * 136 + wm + mt * 16 + lq1 * 8) * 2);
#pragma unroll
            for (int np = 0; np < 4; np++) {
                unsigned r0, r1, r2, r3;
                ldsm4t(r0, r1, r2, r3,
                       bo + ((kb + lq1 * 8 + l7) * 136 + wn + np * 16 + lq2 * 8) * 2);
                unsigned blo[2] = {r0, r1}, bhi[2] = {r2, r3};
#pragma unroll
                for (int mt = 0; mt < 2; mt++) {
                    mma16(acc[mt][2 * np],     a[mt], blo);
                    mma16(acc[mt][2 * np + 1], a[mt], bhi);
                }
            }
        }
        __syncthreads();
    }

    __nv_bfloat16* qb = g_qkvh + (size_t)b * S_ * O3_;
#pragma unroll
    for (int mt = 0; mt < 2; mt++) {
        const int r1 = m0 + wm + mt * 16 + g, r2 = r1 + 8;
#pragma unroll
        for (int nt = 0; nt < 8; nt++) {
            const int cn = n0 + wn + nt * 8 + 2 * t;
            const float b0 = bp[cn], b1 = bp[cn + 1];
            *(__nv_bfloat162*)&qb[(size_t)r1 * O3_ + cn] =
                __floats2bfloat162_rn(acc[mt][nt][0] + b0, acc[mt][nt][1] + b1);
            *(__nv_bfloat162*)&qb[(size_t)r2 * O3_ + cn] =
                __floats2bfloat162_rn(acc[mt][nt][2] + b0, acc[mt][nt][3] + b1);
        }
    }
}

// ---------------------------------------------------------------------------
// Kernel 2: flash attention, 2-stage cp.async on K/V tiles, P in registers.
// ---------------------------------------------------------------------------
#define KVS 9216u   // 64*72*2 bytes per stage
__global__ void __launch_bounds__(256, 2) attn_kernel() {
    __shared__ __align__(16) __nv_bfloat16 sm[4 * 64 * 72];  // K[2] then V[2]
    const int i0 = blockIdx.x * 128;
    const int h  = blockIdx.y;
    const int b  = blockIdx.z;
    const __nv_bfloat16* qkv = g_qkvh + (size_t)b * S_ * O3_;

    const int tid = threadIdx.x, warp = tid >> 5, lane = tid & 31;
    const int g = lane >> 2, t = lane & 3;
    const int l7 = lane & 7, lq1 = (lane >> 3) & 1, lq2 = (lane >> 4) & 1;
    const unsigned ks_b = smem_u32(sm), vs_b = ks_b + 2 * KVS;
    const float k2 = SCALE_ * LOG2E_;

    const int lj = tid >> 2, lc = (tid & 3) * 8;   // loader: 4 chunks of 8 per 32-cols? no: 64 cols
    // 64 rows x 64 cols: each row = 8 chunks of 8. 256 threads: rows tid>>2? that covers 64 rows x 4 chunks.
    // Need 2 passes of 4 chunks: c = (tid&3)*8 and +32.

    unsigned qa[4][4];
    {
        const __nv_bfloat16* q1 = qkv + (size_t)(i0 + warp * 16 + g) * O3_ + h * 192;
        const __nv_bfloat16* q2 = q1 + 8 * O3_;
#pragma unroll
        for (int c = 0; c < 4; c++) {
            qa[c][0] = *(const unsigned*)&q1[c * 16 + 2 * t];
            qa[c][1] = *(const unsigned*)&q2[c * 16 + 2 * t];
            qa[c][2] = *(const unsigned*)&q1[c * 16 + 8 + 2 * t];
            qa[c][3] = *(const unsigned*)&q2[c * 16 + 8 + 2 * t];
        }
    }

    float oacc[8][4];
#pragma unroll
    for (int nt = 0; nt < 8; nt++)
#pragma unroll
        for (int i = 0; i < 4; i++) oacc[nt][i] = 0.f;
    float m1 = -1e30f, m2 = -1e30f, l1 = 0.f, l2 = 0.f;

    // issue tile 0
    {
        const __nv_bfloat16* src = qkv + (size_t)lj * O3_ + h * 192 + 64;
        CP16(ks_b + (lj * 72 + lc) * 2,        src + lc);
        CP16(ks_b + (lj * 72 + lc + 32) * 2,   src + lc + 32);
        CP16(vs_b + (lj * 72 + lc) * 2,        src + 64 + lc);
        CP16(vs_b + (lj * 72 + lc + 32) * 2,   src + 64 + lc + 32);
        CPCOMMIT();
    }

    for (int jt = 0; jt < 16; jt++) {
        if (jt + 1 < 16) {
            const unsigned ko = ks_b + ((jt + 1) & 1) * KVS;
            const unsigned vo = vs_b + ((jt + 1) & 1) * KVS;
            const __nv_bfloat16* src = qkv + (size_t)((jt + 1) * 64 + lj) * O3_ + h * 192 + 64;
            CP16(ko + (lj * 72 + lc) * 2,      src + lc);
            CP16(ko + (lj * 72 + lc + 32) * 2, src + lc + 32);
            CP16(vo + (lj * 72 + lc) * 2,      src + 64 + lc);
            CP16(vo + (lj * 72 + lc + 32) * 2, src + 64 + lc + 32);
            CPCOMMIT();
            CPWAIT1();
        } else {
            CPWAIT0();
        }
        __syncthreads();
        const unsigned ko = ks_b + (jt & 1) * KVS;
        const unsigned vo = vs_b + (jt & 1) * KVS;

        float sacc[8][4];
#pragma unroll
        for (int nt = 0; nt < 8; nt++)
#pragma unroll
            for (int i = 0; i < 4; i++) sacc[nt][i] = 0.f;
#pragma unroll
        for (int c = 0; c < 4; c++) {
            const int kb = c * 16;
#pragma unroll
            for (int np = 0; np < 4; np++) {
                unsigned r0, r1, r2, r3;
                ldsm4(r0, r1, r2, r3,
                      ko + ((np * 16 + lq2 * 8 + l7) * 72 + kb + lq1 * 8) * 2);
                unsigned blo[2] = {r0, r1}, bhi[2] = {r2, r3};
                mma16(sacc[2 * np],     qa[c], blo);
                mma16(sacc[2 * np + 1], qa[c], bhi);
            }
        }

        float mx1 = -1e30f, mx2 = -1e30f;
#pragma unroll
        for (int nt = 0; nt < 8; nt++) {
            mx1 = fmaxf(mx1, fmaxf(sacc[nt][0], sacc[nt][1]));
            mx2 = fmaxf(mx2, fmaxf(sacc[nt][2], sacc[nt][3]));
        }
        mx1 = fmaxf(mx1, __shfl_xor_sync(0xffffffffu, mx1, 1));
        mx1 = fmaxf(mx1, __shfl_xor_sync(0xffffffffu, mx1, 2));
        mx2 = fmaxf(mx2, __shfl_xor_sync(0xffffffffu, mx2, 1));
        mx2 = fmaxf(mx2, __shfl_xor_sync(0xffffffffu, mx2, 2));
        const float mn1 = fmaxf(m1, mx1), mn2 = fmaxf(m2, mx2);
        const float al1 = exp2fast((m1 - mn1) * k2), al2 = exp2fast((m2 - mn2) * k2);
        m1 = mn1; m2 = mn2;

        float s1 = 0.f, s2 = 0.f;
        unsigned pa[4][4];
#pragma unroll
        for (int jc = 0; jc < 4; jc++) {
            float p0 = exp2fast((sacc[2 * jc][0] - mn1) * k2);
            float p1 = exp2fast((sacc[2 * jc][1] - mn1) * k2);
            float p2 = exp2fast((sacc[2 * jc][2] - mn2) * k2);
            float p3 = exp2fast((sacc[2 * jc][3] - mn2) * k2);
            float p4 = exp2fast((sacc[2 * jc + 1][0] - mn1) * k2);
            float p5 = exp2fast((sacc[2 * jc + 1][1] - mn1) * k2);
            float p6 = exp2fast((sacc[2 * jc + 1][2] - mn2) * k2);
            float p7 = exp2fast((sacc[2 * jc + 1][3] - mn2) * k2);
            s1 += (p0 + p1) + (p4 + p5);
            s2 += (p2 + p3) + (p6 + p7);
            pa[jc][0] = packbf(p0, p1);
            pa[jc][1] = packbf(p2, p3);
            pa[jc][2] = packbf(p4, p5);
            pa[jc][3] = packbf(p6, p7);
        }
        s1 += __shfl_xor_sync(0xffffffffu, s1, 1);
        s1 += __shfl_xor_sync(0xffffffffu, s1, 2);
        s2 += __shfl_xor_sync(0xffffffffu, s2, 1);
        s2 += __shfl_xor_sync(0xffffffffu, s2, 2);
        l1 = l1 * al1 + s1;
        l2 = l2 * al2 + s2;
#pragma unroll
        for (int nt = 0; nt < 8; nt++) {
            oacc[nt][0] *= al1; oacc[nt][1] *= al1;
            oacc[nt][2] *= al2; oacc[nt][3] *= al2;
        }

#pragma unroll
        for (int jc = 0; jc < 4; jc++) {
            const int kc = jc * 16;
#pragma unroll
            for (int dp = 0; dp < 4; dp++) {
                unsigned r0, r1, r2, r3;
                ldsm4t(r0, r1, r2, r3,
                       vo + ((kc + lq1 * 8 + l7) * 72 + dp * 16 + lq2 * 8) * 2);
                unsigned blo[2] = {r0, r1}, bhi[2] = {r2, r3};
                mma16(oacc[2 * dp],     pa[jc], blo);
                mma16(oacc[2 * dp + 1], pa[jc], bhi);
            }
        }
        __syncthreads();
    }

    const float inv1 = 1.f / l1, inv2 = 1.f / l2;
    __nv_bfloat16* ob1 = g_aoh + (size_t)b * S_ * C_
                       + (size_t)(i0 + warp * 16 + g) * C_ + h * 64;
    __nv_bfloat16* ob2 = ob1 + 8 * C_;
#pragma unroll
    for (int nt = 0; nt < 8; nt++) {
        *(__nv_bfloat162*)&ob1[nt * 8 + 2 * t] =
            __floats2bfloat162_rn(oacc[nt][0] * inv1, oacc[nt][1] * inv1);
        *(__nv_bfloat162*)&ob2[nt * 8 + 2 * t] =
            __floats2bfloat162_rn(oacc[nt][2] * inv2, oacc[nt][3] * inv2);
    }
}

// ---------------------------------------------------------------------------
// Kernel 3: out = g_aoh @ w_out + b_out + x, transposed store, 2-stage pipeline.
// ---------------------------------------------------------------------------
#define OAS 10240u  // 128*40*2
#define OBS 8704u   // 32*136*2
__global__ void __launch_bounds__(256, 2) out_gemm(const float* __restrict__ bo,
                                                   const float* __restrict__ x,
                                                   float* __restrict__ out) {
    __shared__ __align__(16) __nv_bfloat16 sm[(2 * 10240 + 2 * 8704) / 2];
    const int b  = blockIdx.z;
    const int m0 = blockIdx.y * 128;
    const int n0 = blockIdx.x * 128;
    const int tid = threadIdx.x, warp = tid >> 5, lane = tid & 31;
    const int g = lane >> 2, t = lane & 3;
    const int l7 = lane & 7, lq1 = (lane >> 3) & 1, lq2 = (lane >> 4) & 1;
    const int wm = (warp >> 1) * 32, wn = (warp & 1) * 64;
    const __nv_bfloat16* ab = g_aoh + (size_t)b * S_ * C_;
    const unsigned as_b = smem_u32(sm), bs_b = as_b + 2 * OAS;

    const int am = tid >> 1, ac = (tid & 1) * 16;        // A loader: 128 rows x 2 chunks(16)
    const int bkk = tid >> 4, bc = (tid & 15) * 8;       // B loader

    float acc[2][8][4];
#pragma unroll
    for (int mt = 0; mt < 2; mt++)
#pragma unroll
        for (int nt = 0; nt < 8; nt++)
#pragma unroll
            for (int i = 0; i < 4; i++) acc[mt][nt][i] = 0.f;

    {
        CP16(as_b + (am * 40 + ac) * 2,      ab + (size_t)(m0 + am) * C_ + ac);
        CP16(as_b + (am * 40 + ac + 8) * 2,  ab + (size_t)(m0 + am) * C_ + ac + 8);
        CP16(bs_b + (bkk * 136 + bc) * 2,        g_woh + (size_t)bkk * C_ + n0 + bc);
        CP16(bs_b + ((bkk + 16) * 136 + bc) * 2, g_woh + (size_t)(bkk + 16) * C_ + n0 + bc);
        CPCOMMIT();
    }

    for (int it = 0; it < 8; it++) {
        if (it + 1 < 8) {
            const int k0 = (it + 1) * 32;
            const unsigned ao = as_b + ((it + 1) & 1) * OAS;
            const unsigned bo2 = bs_b + ((it + 1) & 1) * OBS;
            CP16(ao + (am * 40 + ac) * 2,     ab + (size_t)(m0 + am) * C_ + k0 + ac);
            CP16(ao + (am * 40 + ac + 8) * 2, ab + (size_t)(m0 + am) * C_ + k0 + ac + 8);
            CP16(bo2 + (bkk * 136 + bc) * 2,        g_woh + (size_t)(k0 + bkk) * C_ + n0 + bc);
            CP16(bo2 + ((bkk + 16) * 136 + bc) * 2, g_woh + (size_t)(k0 + bkk + 16) * C_ + n0 + bc);
            CPCOMMIT();
            CPWAIT1();
        } else {
            CPWAIT0();
        }
        __syncthreads();
        const unsigned ao = as_b + (it & 1) * OAS;
        const unsigned bo2 = bs_b + (it & 1) * OBS;
#pragma unroll
        for (int ks = 0; ks < 2; ks++) {
            const int kb = ks * 16;
            unsigned a[2][4];
#pragma unroll
            for (int mt = 0; mt < 2; mt++)
                ldsm4(a[mt][0], a[mt][1], a[mt][2], a[mt][3],
                      ao + ((wm + mt * 16 + lq1 * 8 + l7) * 40 + kb + lq2 * 8) * 2);
#pragma unroll
            for (int np = 0; np < 4; np++) {
                unsigned r0, r1, r2, r3;
                ldsm4t(r0, r1, r2, r3,
                       bo2 + ((kb + lq1 * 8 + l7) * 136 + wn + np * 16 + lq2 * 8) * 2);
                unsigned blo[2] = {r0, r1}, bhi[2] = {r2, r3};
#pragma unroll
                for (int mt = 0; mt < 2; mt++) {
                    mma16(acc[mt][2 * np],     a[mt], blo);
                    mma16(acc[mt][2 * np + 1], a[mt], bhi);
                }
            }
        }
        __syncthreads();
    }

    const float* xb = x + (size_t)b * C_ * S_;
    float* ob = out + (size_t)b * C_ * S_;
#pragma unroll
    for (int mt = 0; mt < 2; mt++) {
        const int r1 = m0 + wm + mt * 16 + g, r2 = r1 + 8;
#pragma unroll
        for (int nt = 0; nt < 8; nt++) {
            const int c0 = n0 + wn + nt * 8 + 2 * t, c1 = c0 + 1;
            const float bo0 = bo[c0], bo1 = bo[c1];
            ob[(size_t)c0 * S_ + r1] = acc[mt][nt][0] + bo0 + xb[(size_t)c0 * S_ + r1];
            ob[(size_t)c1 * S_ + r1] = acc[mt][nt][1] + bo1 + xb[(size_t)c1 * S_ + r1];
            ob[(size_t)c0 * S_ + r2] = acc[mt][nt][2] + bo0 + xb[(size_t)c0 * S_ + r2];
            ob[(size_t)c1 * S_ + r2] = acc[mt][nt][3] + bo1 + xb[(size_t)c1 * S_ + r2];
        }
    }
}

// ---------------------------------------------------------------------------
extern "C" void kernel_launch(void* const* d_in, const int* in_sizes, int n_in,
                              void* d_out, int out_size) {
    const float* x  = (const float*)d_in[0];
    const float* wp = (const float*)d_in[1];
    const float* bp = (const float*)d_in[2];
    const float* wo = (const float*)d_in[3];
    const float* bo = (const float*)d_in[4];
    float* out = (float*)d_out;

    const int total4 = NX4 + NWP4 + NWO4;
    cvt_inputs<<<(total4 + 255) / 256, 256>>>(x, wp, wo);
    qkv_gemm<<<dim3(O3_ / 128, S_ / 128, B_), 256>>>(bp);
    attn_kernel<<<dim3(S_ / 128, H_, B_), 256>>>();
    out_gemm<<<dim3(C_ / 128, S_ / 128, B_), 256>>>(bo, x, out);
}

// round 6
// speedup vs baseline: 5.1990x; 1.0611x over previous
#include <cuda_runtime.h>
#include <cuda_bf16.h>

#define B_   16
#define C_   256
#define S_   1024
#define H_   4
#define O3_  768
#define SCALE_ 0.125f
#define LOG2E_ 1.4426950408889634f

// bf16 intermediates + pre-converted inputs
__device__ __align__(16) __nv_bfloat16 g_qkvh[B_ * S_ * O3_];  // [b][s][768]
__device__ __align__(16) __nv_bfloat16 g_aoh [B_ * S_ * C_];   // [b][s][256]
__device__ __align__(16) __nv_bfloat16 g_xh  [B_ * C_ * S_];   // [b][c][s]
__device__ __align__(16) __nv_bfloat16 g_wph [C_ * O3_];
__device__ __align__(16) __nv_bfloat16 g_woh [C_ * C_];

// ---------------------------------------------------------------------------
__device__ __forceinline__ unsigned smem_u32(const void* p) {
    return (unsigned)__cvta_generic_to_shared(p);
}
__device__ __forceinline__ void ldsm4(unsigned& r0, unsigned& r1, unsigned& r2, unsigned& r3,
                                      unsigned a) {
    asm volatile("ldmatrix.sync.aligned.m8n8.x4.shared.b16 {%0,%1,%2,%3},[%4];"
                 : "=r"(r0), "=r"(r1), "=r"(r2), "=r"(r3) : "r"(a));
}
__device__ __forceinline__ void ldsm4t(unsigned& r0, unsigned& r1, unsigned& r2, unsigned& r3,
                                       unsigned a) {
    asm volatile("ldmatrix.sync.aligned.m8n8.x4.trans.shared.b16 {%0,%1,%2,%3},[%4];"
                 : "=r"(r0), "=r"(r1), "=r"(r2), "=r"(r3) : "r"(a));
}
__device__ __forceinline__ void mma16(float c[4], const unsigned a[4], const unsigned b[2]) {
    asm volatile("mma.sync.aligned.m16n8k16.row.col.f32.bf16.bf16.f32 "
                 "{%0,%1,%2,%3},{%4,%5,%6,%7},{%8,%9},{%0,%1,%2,%3};"
                 : "+f"(c[0]), "+f"(c[1]), "+f"(c[2]), "+f"(c[3])
                 : "r"(a[0]), "r"(a[1]), "r"(a[2]), "r"(a[3]),
                   "r"(b[0]), "r"(b[1]));
}
#define CP16(dst, src) \
    asm volatile("cp.async.cg.shared.global [%0], [%1], 16;" :: "r"(dst), "l"(src))
#define CPCOMMIT() asm volatile("cp.async.commit_group;")
#define CPWAIT(n)  asm volatile("cp.async.wait_group %0;" :: "n"(n))

__device__ __forceinline__ unsigned packbf(float lo, float hi) {
    __nv_bfloat162 v = __floats2bfloat162_rn(lo, hi);
    return *(unsigned*)&v;
}
__device__ __forceinline__ float exp2fast(float x) {
    x = fmaxf(x, -126.0f);
    float z = x + 12582912.0f;
    int   n = __float_as_int(z) - 0x4B400000;
    float f = x - (z - 12582912.0f);
    float p = 0.0013333558f;
    p = fmaf(p, f, 0.0096181291f);
    p = fmaf(p, f, 0.0555041087f);
    p = fmaf(p, f, 0.2402265070f);
    p = fmaf(p, f, 0.6931471806f);
    p = fmaf(p, f, 1.0f);
    return __int_as_float(__float_as_int(p) + (n << 23));
}

// ---------------------------------------------------------------------------
// Kernel 0: convert x, w_proj, w_out to bf16 (one-shot elementwise, float4).
// ---------------------------------------------------------------------------
#define NX4  (B_ * C_ * S_ / 4)
#define NWP4 (C_ * O3_ / 4)
#define NWO4 (C_ * C_ / 4)
__global__ void __launch_bounds__(256) cvt_inputs(const float* __restrict__ x,
                                                  const float* __restrict__ wp,
                                                  const float* __restrict__ wo) {
    int idx = blockIdx.x * 256 + threadIdx.x;
    const int total = NX4 + NWP4 + NWO4;
    if (idx >= total) return;
    const float* src; __nv_bfloat16* dst; int i;
    if (idx < NX4)              { src = x;  dst = g_xh;  i = idx; }
    else if (idx < NX4 + NWP4)  { src = wp; dst = g_wph; i = idx - NX4; }
    else                        { src = wo; dst = g_woh; i = idx - NX4 - NWP4; }
    float4 v = *(const float4*)&src[i * 4];
    *(__nv_bfloat162*)&dst[i * 4]     = __floats2bfloat162_rn(v.x, v.y);
    *(__nv_bfloat162*)&dst[i * 4 + 2] = __floats2bfloat162_rn(v.z, v.w);
}

// ---------------------------------------------------------------------------
// Kernel 1: QKV projection. CTA tile 128m x 64n, full K=256 resident in smem.
// 4 cp.async commit groups (k-quarters), 4 barriers total.
// A smem: [k=256][136] (trans ldsm), B smem: [k=256][72].
// ---------------------------------------------------------------------------
#define QKV_ASZ 69632u   // 256*136*2
#define QKV_SM  (69632u + 36864u)
__global__ void __launch_bounds__(256, 2) qkv2(const float* __restrict__ bp) {
    extern __shared__ __align__(16) char dsm[];
    const unsigned as = smem_u32(dsm), bs = as + QKV_ASZ;
    const int b  = blockIdx.z;
    const int m0 = blockIdx.y * 128;
    const int n0 = blockIdx.x * 64;
    const int tid = threadIdx.x, warp = tid >> 5, lane = tid & 31;
    const int g = lane >> 2, t = lane & 3;
    const int l7 = lane & 7, lq1 = (lane >> 3) & 1, lq2 = (lane >> 4) & 1;
    const int wm = (warp >> 1) * 32, wn = (warp & 1) * 32;
    const __nv_bfloat16* xb = g_xh + (size_t)b * C_ * S_;

    // issue all 4 k-quarters
#pragma unroll
    for (int q = 0; q < 4; q++) {
        const int kq = q * 64;
#pragma unroll
        for (int p = 0; p < 4; p++) {
            int kk = kq + (tid >> 4) + p * 16;
            int c  = (tid & 15) * 8;
            CP16(as + (kk * 136 + c) * 2, xb + (size_t)kk * S_ + m0 + c);
        }
#pragma unroll
        for (int p = 0; p < 2; p++) {
            int kk = kq + (tid >> 3) + p * 32;
            int c  = (tid & 7) * 8;
            CP16(bs + (kk * 72 + c) * 2, g_wph + (size_t)kk * O3_ + n0 + c);
        }
        CPCOMMIT();
    }

    float acc[2][4][4];
#pragma unroll
    for (int mt = 0; mt < 2; mt++)
#pragma unroll
        for (int nt = 0; nt < 4; nt++)
#pragma unroll
            for (int i = 0; i < 4; i++) acc[mt][nt][i] = 0.f;

#pragma unroll
    for (int q = 0; q < 4; q++) {
        if (q == 0) CPWAIT(3); else if (q == 1) CPWAIT(2);
        else if (q == 2) CPWAIT(1); else CPWAIT(0);
        __syncthreads();
#pragma unroll
        for (int ks = 0; ks < 4; ks++) {
            const int kb = q * 64 + ks * 16;
            unsigned a[2][4];
#pragma unroll
            for (int mt = 0; mt < 2; mt++)
                ldsm4t(a[mt][0], a[mt][1], a[mt][2], a[mt][3],
                       as + ((kb + lq2 * 8 + l7) * 136 + wm + mt * 16 + lq1 * 8) * 2);
#pragma unroll
            for (int np = 0; np < 2; np++) {
                unsigned r0, r1, r2, r3;
                ldsm4t(r0, r1, r2, r3,
                       bs + ((kb + lq1 * 8 + l7) * 72 + wn + np * 16 + lq2 * 8) * 2);
                unsigned blo[2] = {r0, r1}, bhi[2] = {r2, r3};
#pragma unroll
                for (int mt = 0; mt < 2; mt++) {
                    mma16(acc[mt][2 * np],     a[mt], blo);
                    mma16(acc[mt][2 * np + 1], a[mt], bhi);
                }
            }
        }
    }

    // epilogue: bias add -> smem bounce [128][72] bf16 -> coalesced global store
    __syncthreads();
    __nv_bfloat16* Ts = (__nv_bfloat16*)dsm;
#pragma unroll
    for (int mt = 0; mt < 2; mt++) {
        const int r1 = wm + mt * 16 + g, r2 = r1 + 8;
#pragma unroll
        for (int nt = 0; nt < 4; nt++) {
            const int cn = wn + nt * 8 + 2 * t;
            float2 bb = *(const float2*)&bp[n0 + cn];
            *(unsigned*)&Ts[r1 * 72 + cn] = packbf(acc[mt][nt][0] + bb.x, acc[mt][nt][1] + bb.y);
            *(unsigned*)&Ts[r2 * 72 + cn] = packbf(acc[mt][nt][2] + bb.x, acc[mt][nt][3] + bb.y);
        }
    }
    __syncthreads();
    __nv_bfloat16* qb = g_qkvh + (size_t)b * S_ * O3_;
#pragma unroll
    for (int i = 0; i < 4; i++) {
        int idx = tid + i * 256;
        int row = idx >> 3, c16 = (idx & 7) * 8;
        uint4 v = *(uint4*)&Ts[row * 72 + c16];
        *(uint4*)&qb[(size_t)(m0 + row) * O3_ + n0 + c16] = v;
    }
}

// ---------------------------------------------------------------------------
// Kernel 2: flash attention, 3-stage cp.async K/V ring, ONE barrier per j-tile.
// ---------------------------------------------------------------------------
#define KVS 9216u   // 64*72*2 per stage
__global__ void __launch_bounds__(256, 2) attn_kernel() {
    __shared__ __align__(16) __nv_bfloat16 sm[6 * 64 * 72];   // K[3] then V[3]
    const int i0 = blockIdx.x * 128;
    const int h  = blockIdx.y;
    const int b  = blockIdx.z;
    const __nv_bfloat16* qkv = g_qkvh + (size_t)b * S_ * O3_;

    const int tid = threadIdx.x, warp = tid >> 5, lane = tid & 31;
    const int g = lane >> 2, t = lane & 3;
    const int l7 = lane & 7, lq1 = (lane >> 3) & 1, lq2 = (lane >> 4) & 1;
    const unsigned ks_b = smem_u32(sm), vs_b = ks_b + 3 * KVS;
    const float k2 = SCALE_ * LOG2E_;

    const int lj = tid >> 2, lc = (tid & 3) * 8;

    unsigned qa[4][4];
    {
        const __nv_bfloat16* q1 = qkv + (size_t)(i0 + warp * 16 + g) * O3_ + h * 192;
        const __nv_bfloat16* q2 = q1 + 8 * O3_;
#pragma unroll
        for (int c = 0; c < 4; c++) {
            qa[c][0] = *(const unsigned*)&q1[c * 16 + 2 * t];
            qa[c][1] = *(const unsigned*)&q2[c * 16 + 2 * t];
            qa[c][2] = *(const unsigned*)&q1[c * 16 + 8 + 2 * t];
            qa[c][3] = *(const unsigned*)&q2[c * 16 + 8 + 2 * t];
        }
    }

    float oacc[8][4];
#pragma unroll
    for (int nt = 0; nt < 8; nt++)
#pragma unroll
        for (int i = 0; i < 4; i++) oacc[nt][i] = 0.f;
    float m1 = -1e30f, m2 = -1e30f, l1 = 0.f, l2 = 0.f;

    {   // stage 0
        const __nv_bfloat16* src = qkv + (size_t)lj * O3_ + h * 192 + 64;
        CP16(ks_b + (lj * 72 + lc) * 2,      src + lc);
        CP16(ks_b + (lj * 72 + lc + 32) * 2, src + lc + 32);
        CP16(vs_b + (lj * 72 + lc) * 2,      src + 64 + lc);
        CP16(vs_b + (lj * 72 + lc + 32) * 2, src + 64 + lc + 32);
        CPCOMMIT();
    }

    int s_cur = 0, s_nxt = 1;
    for (int jt = 0; jt < 16; jt++) {
        if (jt + 1 < 16) {
            const unsigned ko = ks_b + s_nxt * KVS;
            const unsigned vo = vs_b + s_nxt * KVS;
            const __nv_bfloat16* src = qkv + (size_t)((jt + 1) * 64 + lj) * O3_ + h * 192 + 64;
            CP16(ko + (lj * 72 + lc) * 2,      src + lc);
            CP16(ko + (lj * 72 + lc + 32) * 2, src + lc + 32);
            CP16(vo + (lj * 72 + lc) * 2,      src + 64 + lc);
            CP16(vo + (lj * 72 + lc + 32) * 2, src + 64 + lc + 32);
            CPCOMMIT();
            CPWAIT(1);
        } else {
            CPWAIT(0);
        }
        __syncthreads();
        const unsigned ko = ks_b + s_cur * KVS;
        const unsigned vo = vs_b + s_cur * KVS;

        float sacc[8][4];
#pragma unroll
        for (int nt = 0; nt < 8; nt++)
#pragma unroll
            for (int i = 0; i < 4; i++) sacc[nt][i] = 0.f;
#pragma unroll
        for (int c = 0; c < 4; c++) {
            const int kb = c * 16;
#pragma unroll
            for (int np = 0; np < 4; np++) {
                unsigned r0, r1, r2, r3;
                ldsm4(r0, r1, r2, r3,
                      ko + ((np * 16 + lq2 * 8 + l7) * 72 + kb + lq1 * 8) * 2);
                unsigned blo[2] = {r0, r1}, bhi[2] = {r2, r3};
                mma16(sacc[2 * np],     qa[c], blo);
                mma16(sacc[2 * np + 1], qa[c], bhi);
            }
        }

        float mx1 = -1e30f, mx2 = -1e30f;
#pragma unroll
        for (int nt = 0; nt < 8; nt++) {
            mx1 = fmaxf(mx1, fmaxf(sacc[nt][0], sacc[nt][1]));
            mx2 = fmaxf(mx2, fmaxf(sacc[nt][2], sacc[nt][3]));
        }
        mx1 = fmaxf(mx1, __shfl_xor_sync(0xffffffffu, mx1, 1));
        mx1 = fmaxf(mx1, __shfl_xor_sync(0xffffffffu, mx1, 2));
        mx2 = fmaxf(mx2, __shfl_xor_sync(0xffffffffu, mx2, 1));
        mx2 = fmaxf(mx2, __shfl_xor_sync(0xffffffffu, mx2, 2));
        const float mn1 = fmaxf(m1, mx1), mn2 = fmaxf(m2, mx2);
        const float al1 = exp2fast((m1 - mn1) * k2), al2 = exp2fast((m2 - mn2) * k2);
        m1 = mn1; m2 = mn2;

        float s1 = 0.f, s2 = 0.f;
        unsigned pa[4][4];
#pragma unroll
        for (int jc = 0; jc < 4; jc++) {
            float p0 = exp2fast((sacc[2 * jc][0] - mn1) * k2);
            float p1 = exp2fast((sacc[2 * jc][1] - mn1) * k2);
            float p2 = exp2fast((sacc[2 * jc][2] - mn2) * k2);
            float p3 = exp2fast((sacc[2 * jc][3] - mn2) * k2);
            float p4 = exp2fast((sacc[2 * jc + 1][0] - mn1) * k2);
            float p5 = exp2fast((sacc[2 * jc + 1][1] - mn1) * k2);
            float p6 = exp2fast((sacc[2 * jc + 1][2] - mn2) * k2);
            float p7 = exp2fast((sacc[2 * jc + 1][3] - mn2) * k2);
            s1 += (p0 + p1) + (p4 + p5);
            s2 += (p2 + p3) + (p6 + p7);
            pa[jc][0] = packbf(p0, p1);
            pa[jc][1] = packbf(p2, p3);
            pa[jc][2] = packbf(p4, p5);
            pa[jc][3] = packbf(p6, p7);
        }
        s1 += __shfl_xor_sync(0xffffffffu, s1, 1);
        s1 += __shfl_xor_sync(0xffffffffu, s1, 2);
        s2 += __shfl_xor_sync(0xffffffffu, s2, 1);
        s2 += __shfl_xor_sync(0xffffffffu, s2, 2);
        l1 = l1 * al1 + s1;
        l2 = l2 * al2 + s2;
#pragma unroll
        for (int nt = 0; nt < 8; nt++) {
            oacc[nt][0] *= al1; oacc[nt][1] *= al1;
            oacc[nt][2] *= al2; oacc[nt][3] *= al2;
        }

#pragma unroll
        for (int jc = 0; jc < 4; jc++) {
            const int kc = jc * 16;
#pragma unroll
            for (int dp = 0; dp < 4; dp++) {
                unsigned r0, r1, r2, r3;
                ldsm4t(r0, r1, r2, r3,
                       vo + ((kc + lq1 * 8 + l7) * 72 + dp * 16 + lq2 * 8) * 2);
                unsigned blo[2] = {r0, r1}, bhi[2] = {r2, r3};
                mma16(oacc[2 * dp],     pa[jc], blo);
                mma16(oacc[2 * dp + 1], pa[jc], bhi);
            }
        }
        s_cur = s_nxt;
        s_nxt = (s_nxt == 2) ? 0 : s_nxt + 1;
    }

    const float inv1 = 1.f / l1, inv2 = 1.f / l2;
    __nv_bfloat16* ob1 = g_aoh + (size_t)b * S_ * C_
                       + (size_t)(i0 + warp * 16 + g) * C_ + h * 64;
    __nv_bfloat16* ob2 = ob1 + 8 * C_;
#pragma unroll
    for (int nt = 0; nt < 8; nt++) {
        *(__nv_bfloat162*)&ob1[nt * 8 + 2 * t] =
            __floats2bfloat162_rn(oacc[nt][0] * inv1, oacc[nt][1] * inv1);
        *(__nv_bfloat162*)&ob2[nt * 8 + 2 * t] =
            __floats2bfloat162_rn(oacc[nt][2] * inv2, oacc[nt][3] * inv2);
    }
}

// ---------------------------------------------------------------------------
// Kernel 3: out projection + bias + residual + transpose. CTA 128m x 64n,
// full K=256 resident. A smem [m=128][264] (non-trans), B smem [k=256][72].
// ---------------------------------------------------------------------------
#define OUT_ASZ 67584u   // 128*264*2
#define OUT_SM  (67584u + 36864u)
__global__ void __launch_bounds__(256, 2) out2(const float* __restrict__ bo,
                                               const float* __restrict__ x,
                                               float* __restrict__ out) {
    extern __shared__ __align__(16) char dsm[];
    const unsigned as = smem_u32(dsm), bs = as + OUT_ASZ;
    const int b  = blockIdx.z;
    const int m0 = blockIdx.y * 128;
    const int n0 = blockIdx.x * 64;
    const int tid = threadIdx.x, warp = tid >> 5, lane = tid & 31;
    const int g = lane >> 2, t = lane & 3;
    const int l7 = lane & 7, lq1 = (lane >> 3) & 1, lq2 = (lane >> 4) & 1;
    const int wm = (warp >> 1) * 32, wn = (warp & 1) * 32;
    const __nv_bfloat16* ab = g_aoh + (size_t)b * S_ * C_;

#pragma unroll
    for (int q = 0; q < 4; q++) {
        const int kq = q * 64;
#pragma unroll
        for (int p = 0; p < 4; p++) {
            int m  = tid >> 1;
            int kc = kq + (tid & 1) * 8 + p * 16;
            CP16(as + (m * 264 + kc) * 2, ab + (size_t)(m0 + m) * C_ + kc);
        }
#pragma unroll
        for (int p = 0; p < 2; p++) {
            int kk = kq + (tid >> 3) + p * 32;
            int c  = (tid & 7) * 8;
            CP16(bs + (kk * 72 + c) * 2, g_woh + (size_t)kk * C_ + n0 + c);
        }
        CPCOMMIT();
    }

    float acc[2][4][4];
#pragma unroll
    for (int mt = 0; mt < 2; mt++)
#pragma unroll
        for (int nt = 0; nt < 4; nt++)
#pragma unroll
            for (int i = 0; i < 4; i++) acc[mt][nt][i] = 0.f;

#pragma unroll
    for (int q = 0; q < 4; q++) {
        if (q == 0) CPWAIT(3); else if (q == 1) CPWAIT(2);
        else if (q == 2) CPWAIT(1); else CPWAIT(0);
        __syncthreads();
#pragma unroll
        for (int ks = 0; ks < 4; ks++) {
            const int kb = q * 64 + ks * 16;
            unsigned a[2][4];
#pragma unroll
            for (int mt = 0; mt < 2; mt++)
                ldsm4(a[mt][0], a[mt][1], a[mt][2], a[mt][3],
                      as + ((wm + mt * 16 + lq1 * 8 + l7) * 264 + kb + lq2 * 8) * 2);
#pragma unroll
            for (int np = 0; np < 2; np++) {
                unsigned r0, r1, r2, r3;
                ldsm4t(r0, r1, r2, r3,
                       bs + ((kb + lq1 * 8 + l7) * 72 + wn + np * 16 + lq2 * 8) * 2);
                unsigned blo[2] = {r0, r1}, bhi[2] = {r2, r3};
#pragma unroll
                for (int mt = 0; mt < 2; mt++) {
                    mma16(acc[mt][2 * np],     a[mt], blo);
                    mma16(acc[mt][2 * np + 1], a[mt], bhi);
                }
            }
        }
    }

    // epilogue: stage fp32 [n=64][132] in smem, then coalesced bias+residual+store
    __syncthreads();
    float* Os = (float*)dsm;
#pragma unroll
    for (int mt = 0; mt < 2; mt++) {
        const int r1 = wm + mt * 16 + g, r2 = r1 + 8;
#pragma unroll
        for (int nt = 0; nt < 4; nt++) {
            const int cn = wn + nt * 8 + 2 * t;
            Os[cn * 132 + r1]       = acc[mt][nt][0];
            Os[(cn + 1) * 132 + r1] = acc[mt][nt][1];
            Os[cn * 132 + r2]       = acc[mt][nt][2];
            Os[(cn + 1) * 132 + r2] = acc[mt][nt][3];
        }
    }
    __syncthreads();
    const float* xb = x + (size_t)b * C_ * S_;
    float* ob = out + (size_t)b * C_ * S_;
#pragma unroll
    for (int i = 0; i < 8; i++) {
        int idx = tid + i * 256;
        int row = idx >> 5, c4 = (idx & 31) * 4;
        const int ch = n0 + row;
        const float bias = bo[ch];
        float4 v = *(float4*)&Os[row * 132 + c4];
        float4 xr = *(const float4*)&xb[(size_t)ch * S_ + m0 + c4];
        v.x += bias + xr.x; v.y += bias + xr.y;
        v.z += bias + xr.z; v.w += bias + xr.w;
        *(float4*)&ob[(size_t)ch * S_ + m0 + c4] = v;
    }
}

// ---------------------------------------------------------------------------
extern "C" void kernel_launch(void* const* d_in, const int* in_sizes, int n_in,
                              void* d_out, int out_size) {
    const float* x  = (const float*)d_in[0];
    const float* wp = (const float*)d_in[1];
    const float* bp = (const float*)d_in[2];
    const float* wo = (const float*)d_in[3];
    const float* bo = (const float*)d_in[4];
    float* out = (float*)d_out;

    static int attr_set = 0;
    if (!attr_set) {
        cudaFuncSetAttribute(qkv2, cudaFuncAttributeMaxDynamicSharedMemorySize, (int)QKV_SM);
        cudaFuncSetAttribute(out2, cudaFuncAttributeMaxDynamicSharedMemorySize, (int)OUT_SM);
        attr_set = 1;
    }

    const int total4 = NX4 + NWP4 + NWO4;
    cvt_inputs<<<(total4 + 255) / 256, 256>>>(x, wp, wo);
    qkv2<<<dim3(O3_ / 64, S_ / 128, B_), 256, QKV_SM>>>(bp);
    attn_kernel<<<dim3(S_ / 128, H_, B_), 256>>>();
    out2<<<dim3(C_ / 64, S_ / 128, B_), 256, OUT_SM>>>(bo, x, out);
}

// round 8
// speedup vs baseline: 5.3528x; 1.0296x over previous
#include <cuda_runtime.h>
#include <cuda_bf16.h>

#define B_   16
#define C_   256
#define S_   1024
#define H_   4
#define O3_  768
#define SCALE_ 0.125f
#define LOG2E_ 1.4426950408889634f

__device__ __align__(16) __nv_bfloat16 g_qkvh[B_ * S_ * O3_];  // [b][s][768]
__device__ __align__(16) __nv_bfloat16 g_aoh [B_ * S_ * C_];   // [b][s][256]
__device__ __align__(16) __nv_bfloat16 g_xh  [B_ * C_ * S_];   // [b][c][s]
__device__ __align__(16) __nv_bfloat16 g_wph [C_ * O3_];
__device__ __align__(16) __nv_bfloat16 g_woh [C_ * C_];

// ---------------------------------------------------------------------------
__device__ __forceinline__ unsigned smem_u32(const void* p) {
    return (unsigned)__cvta_generic_to_shared(p);
}
__device__ __forceinline__ void ldsm4(unsigned& r0, unsigned& r1, unsigned& r2, unsigned& r3,
                                      unsigned a) {
    asm volatile("ldmatrix.sync.aligned.m8n8.x4.shared.b16 {%0,%1,%2,%3},[%4];"
                 : "=r"(r0), "=r"(r1), "=r"(r2), "=r"(r3) : "r"(a));
}
__device__ __forceinline__ void ldsm4t(unsigned& r0, unsigned& r1, unsigned& r2, unsigned& r3,
                                       unsigned a) {
    asm volatile("ldmatrix.sync.aligned.m8n8.x4.trans.shared.b16 {%0,%1,%2,%3},[%4];"
                 : "=r"(r0), "=r"(r1), "=r"(r2), "=r"(r3) : "r"(a));
}
__device__ __forceinline__ void mma16(float c[4], const unsigned a[4], const unsigned b[2]) {
    asm volatile("mma.sync.aligned.m16n8k16.row.col.f32.bf16.bf16.f32 "
                 "{%0,%1,%2,%3},{%4,%5,%6,%7},{%8,%9},{%0,%1,%2,%3};"
                 : "+f"(c[0]), "+f"(c[1]), "+f"(c[2]), "+f"(c[3])
                 : "r"(a[0]), "r"(a[1]), "r"(a[2]), "r"(a[3]),
                   "r"(b[0]), "r"(b[1]));
}
#define CP16(dst, src) \
    asm volatile("cp.async.cg.shared.global [%0], [%1], 16;" :: "r"(dst), "l"(src))
#define CPCOMMIT() asm volatile("cp.async.commit_group;")
#define CPWAIT(n)  asm volatile("cp.async.wait_group %0;" :: "n"(n))

__device__ __forceinline__ unsigned packbf(float lo, float hi) {
    __nv_bfloat162 v = __floats2bfloat162_rn(lo, hi);
    return *(unsigned*)&v;
}
__device__ __forceinline__ float exp2fast(float x) {
    x = fmaxf(x, -126.0f);
    float z = x + 12582912.0f;
    int   n = __float_as_int(z) - 0x4B400000;
    float f = x - (z - 12582912.0f);
    float p = 0.0013333558f;
    p = fmaf(p, f, 0.0096181291f);
    p = fmaf(p, f, 0.0555041087f);
    p = fmaf(p, f, 0.2402265070f);
    p = fmaf(p, f, 0.6931471806f);
    p = fmaf(p, f, 1.0f);
    return __int_as_float(__float_as_int(p) + (n << 23));
}

// ---------------------------------------------------------------------------
// Kernel 0: convert inputs to bf16.
// ---------------------------------------------------------------------------
#define NX4  (B_ * C_ * S_ / 4)
#define NWP4 (C_ * O3_ / 4)
#define NWO4 (C_ * C_ / 4)
__global__ void __launch_bounds__(256) cvt_inputs(const float* __restrict__ x,
                                                  const float* __restrict__ wp,
                                                  const float* __restrict__ wo) {
    int idx = blockIdx.x * 256 + threadIdx.x;
    const int total = NX4 + NWP4 + NWO4;
    if (idx >= total) return;
    const float* src; __nv_bfloat16* dst; int i;
    if (idx < NX4)              { src = x;  dst = g_xh;  i = idx; }
    else if (idx < NX4 + NWP4)  { src = wp; dst = g_wph; i = idx - NX4; }
    else                        { src = wo; dst = g_woh; i = idx - NX4 - NWP4; }
    float4 v = *(const float4*)&src[i * 4];
    *(__nv_bfloat162*)&dst[i * 4]     = __floats2bfloat162_rn(v.x, v.y);
    *(__nv_bfloat162*)&dst[i * 4 + 2] = __floats2bfloat162_rn(v.z, v.w);
}

// ---------------------------------------------------------------------------
// Kernel 1: QKV projection. CTA 128m x 128n, k-chunks 64, 3-stage cp.async ring.
// ---------------------------------------------------------------------------
#define Q_ST 17408u                       // one stage: 64*136*2
#define Q_SM (6u * Q_ST)                  // 104448
__global__ void __launch_bounds__(256, 2) qkv3(const float* __restrict__ bp) {
    extern __shared__ __align__(16) char dsm[];
    const unsigned sa = smem_u32(dsm), sbb = sa + 3 * Q_ST;
    const int b  = blockIdx.z;
    const int m0 = blockIdx.y * 128;
    const int n0 = blockIdx.x * 128;
    const int tid = threadIdx.x, warp = tid >> 5, lane = tid & 31;
    const int g = lane >> 2, t = lane & 3;
    const int l7 = lane & 7, lq1 = (lane >> 3) & 1, lq2 = (lane >> 4) & 1;
    const int wm = (warp >> 1) * 32, wn = (warp & 1) * 64;
    const __nv_bfloat16* xb = g_xh + (size_t)b * C_ * S_;

    const int lk = tid >> 4, lc = (tid & 15) * 8;

#pragma unroll
    for (int p = 0; p < 4; p++) {
        int kk = lk + p * 16;
        CP16(sa  + (kk * 136 + lc) * 2, xb + (size_t)kk * S_ + m0 + lc);
        CP16(sbb + (kk * 136 + lc) * 2, g_wph + (size_t)kk * O3_ + n0 + lc);
    }
    CPCOMMIT();

    float acc[2][8][4];
#pragma unroll
    for (int mt = 0; mt < 2; mt++)
#pragma unroll
        for (int nt = 0; nt < 8; nt++)
#pragma unroll
            for (int i = 0; i < 4; i++) acc[mt][nt][i] = 0.f;

#pragma unroll
    for (int it = 0; it < 4; it++) {
        if (it + 1 < 4) {
            const int k0 = (it + 1) * 64;
            const unsigned ao = sa  + ((it + 1) % 3) * Q_ST;
            const unsigned bo = sbb + ((it + 1) % 3) * Q_ST;
#pragma unroll
            for (int p = 0; p < 4; p++) {
                int kk = lk + p * 16;
                CP16(ao + (kk * 136 + lc) * 2, xb + (size_t)(k0 + kk) * S_ + m0 + lc);
                CP16(bo + (kk * 136 + lc) * 2, g_wph + (size_t)(k0 + kk) * O3_ + n0 + lc);
            }
            CPCOMMIT();
            CPWAIT(1);
        } else {
            CPWAIT(0);
        }
        __syncthreads();
        const unsigned ao = sa  + (it % 3) * Q_ST;
        const unsigned bo = sbb + (it % 3) * Q_ST;
#pragma unroll
        for (int ks = 0; ks < 4; ks++) {
            const int kb = ks * 16;
            unsigned a[2][4];
#pragma unroll
            for (int mt = 0; mt < 2; mt++)
                ldsm4t(a[mt][0], a[mt][1], a[mt][2], a[mt][3],
                       ao + ((kb + lq2 * 8 + l7) * 136 + wm + mt * 16 + lq1 * 8) * 2);
#pragma unroll
            for (int np = 0; np < 4; np++) {
                unsigned r0, r1, r2, r3;
                ldsm4t(r0, r1, r2, r3,
                       bo + ((kb + lq1 * 8 + l7) * 136 + wn + np * 16 + lq2 * 8) * 2);
                unsigned blo[2] = {r0, r1}, bhi[2] = {r2, r3};
#pragma unroll
                for (int mt = 0; mt < 2; mt++) {
                    mma16(acc[mt][2 * np],     a[mt], blo);
                    mma16(acc[mt][2 * np + 1], a[mt], bhi);
                }
            }
        }
    }

    __syncthreads();
    __nv_bfloat16* Ts = (__nv_bfloat16*)dsm;
#pragma unroll
    for (int mt = 0; mt < 2; mt++) {
        const int r1 = wm + mt * 16 + g, r2 = r1 + 8;
#pragma unroll
        for (int nt = 0; nt < 8; nt++) {
            const int cn = wn + nt * 8 + 2 * t;
            float2 bb = *(const float2*)&bp[n0 + cn];
            *(unsigned*)&Ts[r1 * 136 + cn] = packbf(acc[mt][nt][0] + bb.x, acc[mt][nt][1] + bb.y);
            *(unsigned*)&Ts[r2 * 136 + cn] = packbf(acc[mt][nt][2] + bb.x, acc[mt][nt][3] + bb.y);
        }
    }
    __syncthreads();
    __nv_bfloat16* qb = g_qkvh + (size_t)b * S_ * O3_;
#pragma unroll
    for (int i = 0; i < 8; i++) {
        int idx = tid + i * 256;
        int row = idx >> 4, c16 = (idx & 15) * 8;
        uint4 v = *(uint4*)&Ts[row * 136 + c16];
        *(uint4*)&qb[(size_t)(m0 + row) * O3_ + n0 + c16] = v;
    }
}

// ---------------------------------------------------------------------------
// Kernel 2: flash attention. 512 threads, i-tile 256, 3-stage K/V ring.
// ---------------------------------------------------------------------------
#define KVS 9216u
__global__ void __launch_bounds__(512, 1) attn_kernel() {
    __shared__ __align__(16) __nv_bfloat16 sm[6 * 64 * 72];   // K[3] then V[3]
    const int i0 = blockIdx.x * 256;
    const int h  = blockIdx.y;
    const int b  = blockIdx.z;
    const __nv_bfloat16* qkv = g_qkvh + (size_t)b * S_ * O3_;

    const int tid = threadIdx.x, warp = tid >> 5, lane = tid & 31;
    const int g = lane >> 2, t = lane & 3;
    const int l7 = lane & 7, lq1 = (lane >> 3) & 1, lq2 = (lane >> 4) & 1;
    const unsigned ks_b = smem_u32(sm), vs_b = ks_b + 3 * KVS;
    const float k2 = SCALE_ * LOG2E_;

    const int lj = tid >> 3, lc = (tid & 7) * 8;

    unsigned qa[4][4];
    {
        const __nv_bfloat16* q1 = qkv + (size_t)(i0 + warp * 16 + g) * O3_ + h * 192;
        const __nv_bfloat16* q2 = q1 + 8 * O3_;
#pragma unroll
        for (int c = 0; c < 4; c++) {
            qa[c][0] = *(const unsigned*)&q1[c * 16 + 2 * t];
            qa[c][1] = *(const unsigned*)&q2[c * 16 + 2 * t];
            qa[c][2] = *(const unsigned*)&q1[c * 16 + 8 + 2 * t];
            qa[c][3] = *(const unsigned*)&q2[c * 16 + 8 + 2 * t];
        }
    }

    float oacc[8][4];
#pragma unroll
    for (int nt = 0; nt < 8; nt++)
#pragma unroll
        for (int i = 0; i < 4; i++) oacc[nt][i] = 0.f;
    float m1 = -1e30f, m2 = -1e30f, l1 = 0.f, l2 = 0.f;

    {   // tile 0 -> stage 0  (FIX: include +lc column offset)
        const __nv_bfloat16* src = qkv + (size_t)lj * O3_ + h * 192 + 64 + lc;
        CP16(ks_b + (lj * 72 + lc) * 2, src);
        CP16(vs_b + (lj * 72 + lc) * 2, src + 64);
        CPCOMMIT();
    }

    for (int jt = 0; jt < 16; jt++) {
        if (jt + 1 < 16) {
            const unsigned ko = ks_b + ((jt + 1) % 3) * KVS;
            const unsigned vo = vs_b + ((jt + 1) % 3) * KVS;
            const __nv_bfloat16* src = qkv + (size_t)((jt + 1) * 64 + lj) * O3_ + h * 192 + 64 + lc;
            CP16(ko + (lj * 72 + lc) * 2, src);
            CP16(vo + (lj * 72 + lc) * 2, src + 64);
            CPCOMMIT();
            CPWAIT(1);
        } else {
            CPWAIT(0);
        }
        __syncthreads();
        const unsigned ko = ks_b + (jt % 3) * KVS;
        const unsigned vo = vs_b + (jt % 3) * KVS;

        float sacc[8][4];
#pragma unroll
        for (int nt = 0; nt < 8; nt++)
#pragma unroll
            for (int i = 0; i < 4; i++) sacc[nt][i] = 0.f;
#pragma unroll
        for (int c = 0; c < 4; c++) {
            const int kb = c * 16;
#pragma unroll
            for (int np = 0; np < 4; np++) {
                unsigned r0, r1, r2, r3;
                ldsm4(r0, r1, r2, r3,
                      ko + ((np * 16 + lq2 * 8 + l7) * 72 + kb + lq1 * 8) * 2);
                unsigned blo[2] = {r0, r1}, bhi[2] = {r2, r3};
                mma16(sacc[2 * np],     qa[c], blo);
                mma16(sacc[2 * np + 1], qa[c], bhi);
            }
        }

        float mx1 = -1e30f, mx2 = -1e30f;
#pragma unroll
        for (int nt = 0; nt < 8; nt++) {
            mx1 = fmaxf(mx1, fmaxf(sacc[nt][0], sacc[nt][1]));
            mx2 = fmaxf(mx2, fmaxf(sacc[nt][2], sacc[nt][3]));
        }
        mx1 = fmaxf(mx1, __shfl_xor_sync(0xffffffffu, mx1, 1));
        mx1 = fmaxf(mx1, __shfl_xor_sync(0xffffffffu, mx1, 2));
        mx2 = fmaxf(mx2, __shfl_xor_sync(0xffffffffu, mx2, 1));
        mx2 = fmaxf(mx2, __shfl_xor_sync(0xffffffffu, mx2, 2));
        const float mn1 = fmaxf(m1, mx1), mn2 = fmaxf(m2, mx2);
        const float al1 = exp2fast((m1 - mn1) * k2), al2 = exp2fast((m2 - mn2) * k2);
        m1 = mn1; m2 = mn2;

        float s1 = 0.f, s2 = 0.f;
        unsigned pa[4][4];
#pragma unroll
        for (int jc = 0; jc < 4; jc++) {
            float p0 = exp2fast((sacc[2 * jc][0] - mn1) * k2);
            float p1 = exp2fast((sacc[2 * jc][1] - mn1) * k2);
            float p2 = exp2fast((sacc[2 * jc][2] - mn2) * k2);
            float p3 = exp2fast((sacc[2 * jc][3] - mn2) * k2);
            float p4 = exp2fast((sacc[2 * jc + 1][0] - mn1) * k2);
            float p5 = exp2fast((sacc[2 * jc + 1][1] - mn1) * k2);
            float p6 = exp2fast((sacc[2 * jc + 1][2] - mn2) * k2);
            float p7 = exp2fast((sacc[2 * jc + 1][3] - mn2) * k2);
            s1 += (p0 + p1) + (p4 + p5);
            s2 += (p2 + p3) + (p6 + p7);
            pa[jc][0] = packbf(p0, p1);
            pa[jc][1] = packbf(p2, p3);
            pa[jc][2] = packbf(p4, p5);
            pa[jc][3] = packbf(p6, p7);
        }
        s1 += __shfl_xor_sync(0xffffffffu, s1, 1);
        s1 += __shfl_xor_sync(0xffffffffu, s1, 2);
        s2 += __shfl_xor_sync(0xffffffffu, s2, 1);
        s2 += __shfl_xor_sync(0xffffffffu, s2, 2);
        l1 = l1 * al1 + s1;
        l2 = l2 * al2 + s2;
#pragma unroll
        for (int nt = 0; nt < 8; nt++) {
            oacc[nt][0] *= al1; oacc[nt][1] *= al1;
            oacc[nt][2] *= al2; oacc[nt][3] *= al2;
        }

#pragma unroll
        for (int jc = 0; jc < 4; jc++) {
            const int kc = jc * 16;
#pragma unroll
            for (int dp = 0; dp < 4; dp++) {
                unsigned r0, r1, r2, r3;
                ldsm4t(r0, r1, r2, r3,
                       vo + ((kc + lq1 * 8 + l7) * 72 + dp * 16 + lq2 * 8) * 2);
                unsigned blo[2] = {r0, r1}, bhi[2] = {r2, r3};
                mma16(oacc[2 * dp],     pa[jc], blo);
                mma16(oacc[2 * dp + 1], pa[jc], bhi);
            }
        }
    }

    const float inv1 = 1.f / l1, inv2 = 1.f / l2;
    __nv_bfloat16* ob1 = g_aoh + (size_t)b * S_ * C_
                       + (size_t)(i0 + warp * 16 + g) * C_ + h * 64;
    __nv_bfloat16* ob2 = ob1 + 8 * C_;
#pragma unroll
    for (int nt = 0; nt < 8; nt++) {
        *(__nv_bfloat162*)&ob1[nt * 8 + 2 * t] =
            __floats2bfloat162_rn(oacc[nt][0] * inv1, oacc[nt][1] * inv1);
        *(__nv_bfloat162*)&ob2[nt * 8 + 2 * t] =
            __floats2bfloat162_rn(oacc[nt][2] * inv2, oacc[nt][3] * inv2);
    }
}

// ---------------------------------------------------------------------------
// Kernel 3: out projection. CTA 128m x 128n, k-chunks 64, 3-stage ring.
// ---------------------------------------------------------------------------
#define O_AST 18432u                      // 128*72*2
#define O_BST 17408u                      // 64*136*2
#define O_SM  (3u * (O_AST + O_BST))      // 107520
__global__ void __launch_bounds__(256, 2) out3(const float* __restrict__ bo,
                                               const float* __restrict__ x,
                                               float* __restrict__ out) {
    extern __shared__ __align__(16) char dsm[];
    const unsigned sa = smem_u32(dsm), sbb = sa + 3 * O_AST;
    const int b  = blockIdx.z;
    const int m0 = blockIdx.y * 128;
    const int n0 = blockIdx.x * 128;
    const int tid = threadIdx.x, warp = tid >> 5, lane = tid & 31;
    const int g = lane >> 2, t = lane & 3;
    const int l7 = lane & 7, lq1 = (lane >> 3) & 1, lq2 = (lane >> 4) & 1;
    const int wm = (warp >> 1) * 32, wn = (warp & 1) * 64;
    const __nv_bfloat16* ab = g_aoh + (size_t)b * S_ * C_;

    const int am = tid >> 1, ak = (tid & 1) * 8;
    const int bk = tid >> 4, bc = (tid & 15) * 8;

#pragma unroll
    for (int p = 0; p < 4; p++)
        CP16(sa + (am * 72 + ak + p * 16) * 2, ab + (size_t)(m0 + am) * C_ + ak + p * 16);
#pragma unroll
    for (int p = 0; p < 4; p++) {
        int kk = bk + p * 16;
        CP16(sbb + (kk * 136 + bc) * 2, g_woh + (size_t)kk * C_ + n0 + bc);
    }
    CPCOMMIT();

    float acc[2][8][4];
#pragma unroll
    for (int mt = 0; mt < 2; mt++)
#pragma unroll
        for (int nt = 0; nt < 8; nt++)
#pragma unroll
            for (int i = 0; i < 4; i++) acc[mt][nt][i] = 0.f;

#pragma unroll
    for (int it = 0; it < 4; it++) {
        if (it + 1 < 4) {
            const int k0 = (it + 1) * 64;
            const unsigned ao = sa  + ((it + 1) % 3) * O_AST;
            const unsigned bo2 = sbb + ((it + 1) % 3) * O_BST;
#pragma unroll
            for (int p = 0; p < 4; p++)
                CP16(ao + (am * 72 + ak + p * 16) * 2,
                     ab + (size_t)(m0 + am) * C_ + k0 + ak + p * 16);
#pragma unroll
            for (int p = 0; p < 4; p++) {
                int kk = bk + p * 16;
                CP16(bo2 + (kk * 136 + bc) * 2, g_woh + (size_t)(k0 + kk) * C_ + n0 + bc);
            }
            CPCOMMIT();
            CPWAIT(1);
        } else {
            CPWAIT(0);
        }
        __syncthreads();
        const unsigned ao = sa  + (it % 3) * O_AST;
        const unsigned bo2 = sbb + (it % 3) * O_BST;
#pragma unroll
        for (int ks = 0; ks < 4; ks++) {
            const int kb = ks * 16;
            unsigned a[2][4];
#pragma unroll
            for (int mt = 0; mt < 2; mt++)
                ldsm4(a[mt][0], a[mt][1], a[mt][2], a[mt][3],
                      ao + ((wm + mt * 16 + lq1 * 8 + l7) * 72 + kb + lq2 * 8) * 2);
#pragma unroll
            for (int np = 0; np < 4; np++) {
                unsigned r0, r1, r2, r3;
                ldsm4t(r0, r1, r2, r3,
                       bo2 + ((kb + lq1 * 8 + l7) * 136 + wn + np * 16 + lq2 * 8) * 2);
                unsigned blo[2] = {r0, r1}, bhi[2] = {r2, r3};
#pragma unroll
                for (int mt = 0; mt < 2; mt++) {
                    mma16(acc[mt][2 * np],     a[mt], blo);
                    mma16(acc[mt][2 * np + 1], a[mt], bhi);
                }
            }
        }
    }

    __syncthreads();
    float* Os = (float*)dsm;
#pragma unroll
    for (int mt = 0; mt < 2; mt++) {
        const int r1 = wm + mt * 16 + g, r2 = r1 + 8;
#pragma unroll
        for (int nt = 0; nt < 8; nt++) {
            const int cn = wn + nt * 8 + 2 * t;
            Os[cn * 132 + r1]       = acc[mt][nt][0];
            Os[(cn + 1) * 132 + r1] = acc[mt][nt][1];
            Os[cn * 132 + r2]       = acc[mt][nt][2];
            Os[(cn + 1) * 132 + r2] = acc[mt][nt][3];
        }
    }
    __syncthreads();
    const float* xb = x + (size_t)b * C_ * S_;
    float* ob = out + (size_t)b * C_ * S_;
#pragma unroll
    for (int i = 0; i < 16; i++) {
        int idx = tid + i * 256;
        int row = idx >> 5, c4 = (idx & 31) * 4;
        const int ch = n0 + row;
        const float bias = bo[ch];
        float4 v = *(float4*)&Os[row * 132 + c4];
        float4 xr = *(const float4*)&xb[(size_t)ch * S_ + m0 + c4];
        v.x += bias + xr.x; v.y += bias + xr.y;
        v.z += bias + xr.z; v.w += bias + xr.w;
        *(float4*)&ob[(size_t)ch * S_ + m0 + c4] = v;
    }
}

// ---------------------------------------------------------------------------
extern "C" void kernel_launch(void* const* d_in, const int* in_sizes, int n_in,
                              void* d_out, int out_size) {
    const float* x  = (const float*)d_in[0];
    const float* wp = (const float*)d_in[1];
    const float* bp = (const float*)d_in[2];
    const float* wo = (const float*)d_in[3];
    const float* bo = (const float*)d_in[4];
    float* out = (float*)d_out;

    static int attr_set = 0;
    if (!attr_set) {
        cudaFuncSetAttribute(qkv3, cudaFuncAttributeMaxDynamicSharedMemorySize, (int)Q_SM);
        cudaFuncSetAttribute(out3, cudaFuncAttributeMaxDynamicSharedMemorySize, (int)O_SM);
        attr_set = 1;
    }

    const int total4 = NX4 + NWP4 + NWO4;
    cvt_inputs<<<(total4 + 255) / 256, 256>>>(x, wp, wo);
    qkv3<<<dim3(O3_ / 128, S_ / 128, B_), 256, Q_SM>>>(bp);
    attn_kernel<<<dim3(S_ / 256, H_, B_), 512>>>();
    out3<<<dim3(C_ / 128, S_ / 128, B_), 256, O_SM>>>(bo, x, out);
}